// round 15
// baseline (speedup 1.0000x reference)
#include <cuda_runtime.h>
#include <cuda_bf16.h>
#include <math.h>
#include <stdint.h>

#define B_   8
#define T_   16
#define N_   196
#define C_   768
#define H_   8
#define D_   96
#define MEM_ 196
#define HID_ 3072
#define ROWS_ 1568
#define SCALE_ 0.1020620726159657f

typedef __nv_bfloat16 bf16;

// ---------------- fp32 scratch ----------------
__device__ __align__(256) float g_x   [B_*T_*N_*C_];
__device__ __align__(256) float g_cg  [ROWS_*C_];
__device__ __align__(256) float g_memh[ROWS_*C_];
__device__ __align__(256) float g_c2  [ROWS_*C_];
__device__ __align__(256) float g_c2b [ROWS_*C_];
__device__ __align__(256) float g_gate[B_*H_*MEM_];
__device__ __align__(256) float g_ap  [B_*C_];
__device__ __align__(256) float g_bias2[B_*HID_];
__device__ __align__(256) float g_zero[C_];           // zero-init bias for split-K half 2
__device__ __align__(256) float g_memA[ROWS_*C_];
__device__ __align__(256) float g_memB[ROWS_*C_];

// ---------------- augmented bf16 activations ----------------
__device__ __align__(256) uint16_t g_xA  [T_*B_*N_*3*C_];
__device__ __align__(256) uint16_t g_hidCA[ROWS_*3*HID_];
__device__ __align__(256) uint16_t g_hidMA[ROWS_*3*HID_];
__device__ __align__(256) uint16_t g_cgA [ROWS_*3*C_];
__device__ __align__(256) uint16_t g_cA  [ROWS_*3*C_];
__device__ __align__(256) uint16_t g_memAg[ROWS_*3*C_];

// attention aug operands (zero-init; pads never written)
__device__ __align__(256) uint16_t g_Q3 [64*196*384];
__device__ __align__(256) uint16_t g_K3 [64*196*384];
__device__ __align__(256) uint16_t g_oT3[64*196*768];
__device__ __align__(256) uint16_t g_cgT3[64*96*768];

// weights augmented [N][3K] = [hi|lo|hi]
__device__ __align__(256) uint16_t g_wc1[HID_*3*C_];
__device__ __align__(256) uint16_t g_wc2[C_*3*HID_];
__device__ __align__(256) uint16_t g_wm1[HID_*3*C_];
__device__ __align__(256) uint16_t g_wm2[C_*3*HID_];
__device__ __align__(256) uint16_t g_wp1[HID_*3*C_];
__device__ __align__(256) uint16_t g_wp2[C_*3*HID_];
__device__ __align__(256) uint16_t g_wq [C_*3*C_];
__device__ __align__(256) uint16_t g_wk [C_*3*C_];

__device__ __forceinline__ float gelu_exact(float x) {
    return 0.5f * x * (1.0f + erff(x * 0.70710678118654752f));
}
__device__ __forceinline__ uint32_t smem_u32(const void* p) {
    uint32_t a;
    asm("{ .reg .u64 t; cvta.to.shared.u64 t, %1; cvt.u32.u64 %0, t; }" : "=r"(a) : "l"(p));
    return a;
}
__device__ __forceinline__ void cp16(uint32_t dst, const void* src, int pred) {
    int sz = pred ? 16 : 0;
    asm volatile("cp.async.cg.shared.global [%0], [%1], 16, %2;" :: "r"(dst), "l"(src), "r"(sz) : "memory");
}
__device__ __forceinline__ uint32_t swz(uint32_t o) { return o ^ ((o >> 3) & 0x70); }

#define LDSM4(r0, r1, r2, r3, addr) \
    asm volatile("ldmatrix.sync.aligned.m8n8.x4.shared.b16 {%0,%1,%2,%3}, [%4];" \
        : "=r"(r0), "=r"(r1), "=r"(r2), "=r"(r3) : "r"(addr))

#define MMA16816(d, a, b0, b1) \
    asm volatile("mma.sync.aligned.m16n8k16.row.col.f32.bf16.bf16.f32 " \
        "{%0,%1,%2,%3}, {%4,%5,%6,%7}, {%8,%9}, {%0,%1,%2,%3};" \
        : "+f"((d)[0]), "+f"((d)[1]), "+f"((d)[2]), "+f"((d)[3]) \
        : "r"((a)[0]), "r"((a)[1]), "r"((a)[2]), "r"((a)[3]), "r"(b0), "r"(b1))

__device__ __forceinline__ void aug_store(uint16_t* aug, size_t base, int Ncols, int col,
                                          float v0, float v1)
{
    bf16 h0 = __float2bfloat16(v0), h1 = __float2bfloat16(v1);
    __nv_bfloat162 hh = __halves2bfloat162(h0, h1);
    __nv_bfloat162 ll = __halves2bfloat162(__float2bfloat16(v0 - __bfloat162float(h0)),
                                           __float2bfloat16(v1 - __bfloat162float(h1)));
    *(uint32_t*)(aug + base + col)             = *(uint32_t*)&hh;
    *(uint32_t*)(aug + base + Ncols + col)     = *(uint32_t*)&hh;
    *(uint32_t*)(aug + base + 2 * Ncols + col) = *(uint32_t*)&ll;
}

// ==================== GEMM (proven core; ldK decoupled for split-K) ====================
// mode bits: 1=gelu, 2=fp32 out, 4=aug out, 8=per-batch bias, 16=Q3 aug, 32=K3 aug
#define GS 3

template<int BM, int BN, int MT, int NT>
__global__ __launch_bounds__(256, 2) void gemm_mma(
    const bf16* __restrict__ A, const bf16* __restrict__ Bw,
    const float* __restrict__ bias, float* __restrict__ out,
    uint16_t* __restrict__ outAug, int M, int N, int K3, int ldK, int mode)
{
    constexpr int A_BYTES = BM * 128;
    constexpr int STG = (BM + BN) * 128;
    extern __shared__ __align__(1024) char smem[];
    uint32_t sb = smem_u32(smem);
    int tid = threadIdx.x, wid = tid >> 5, lane = tid & 31;
    int bm = blockIdx.y * BM, bn = blockIdx.x * BN;
    int m0w = (wid & 1) * (MT * 16);
    int n0w = (wid >> 1) * (NT * 8);
    int NC = K3 >> 6;

    auto load_stage = [&](int c) {
        uint32_t stage = sb + (c % GS) * STG;
        int k0 = c << 6;
        constexpr int TOT = (BM + BN) * 8;
#pragma unroll
        for (int g0 = 0; g0 < TOT; g0 += 256) {
            int g = g0 + tid;
            int isB = (g >= BM * 8);
            int q = isB ? (g - BM * 8) : g;
            int row = q >> 3, c16 = q & 7;
            uint32_t dst = stage + (isB ? A_BYTES : 0) + swz((row << 7) + (c16 << 4));
            const bf16* src;
            int pred = 1;
            if (!isB) {
                int gr = bm + row; pred = gr < M;
                src = A + (size_t)(pred ? gr : 0) * ldK + k0 + (c16 << 3);
            } else {
                int gr = bn + row;
                src = Bw + (size_t)gr * ldK + k0 + (c16 << 3);
            }
            cp16(dst, src, pred);
        }
        asm volatile("cp.async.commit_group;" ::: "memory");
    };

    float acc[MT][NT][4];
#pragma unroll
    for (int mt = 0; mt < MT; mt++)
#pragma unroll
        for (int nt = 0; nt < NT; nt++)
#pragma unroll
            for (int i = 0; i < 4; i++) acc[mt][nt][i] = 0.f;

    load_stage(0);
    load_stage(1);

    for (int c = 0; c < NC; c++) {
        if (c == NC - 1) asm volatile("cp.async.wait_group 0;" ::: "memory");
        else             asm volatile("cp.async.wait_group 1;" ::: "memory");
        __syncthreads();
        if (c + 2 < NC) load_stage(c + 2);

        uint32_t sA = sb + (c % GS) * STG;
        uint32_t sB = sA + A_BYTES;
#pragma unroll
        for (int ks = 0; ks < 4; ks++) {
            uint32_t a[MT][4], bfr[NT / 2][4];
#pragma unroll
            for (int mt = 0; mt < MT; mt++) {
                int row = m0w + mt * 16 + (lane & 15);
                int ch = ks * 2 + (lane >> 4);
                uint32_t ad = sA + swz((uint32_t)(row << 7) + (ch << 4));
                LDSM4(a[mt][0], a[mt][1], a[mt][2], a[mt][3], ad);
            }
#pragma unroll
            for (int bp = 0; bp < NT / 2; bp++) {
                int row = n0w + bp * 16 + (lane & 7) + ((lane & 16) >> 1);
                int ch = ks * 2 + ((lane & 8) >> 3);
                uint32_t ad = sB + swz((uint32_t)(row << 7) + (ch << 4));
                LDSM4(bfr[bp][0], bfr[bp][1], bfr[bp][2], bfr[bp][3], ad);
            }
#pragma unroll
            for (int mt = 0; mt < MT; mt++)
#pragma unroll
                for (int nt = 0; nt < NT; nt++)
                    MMA16816(acc[mt][nt], a[mt],
                             bfr[nt >> 1][(nt & 1) * 2], bfr[nt >> 1][(nt & 1) * 2 + 1]);
        }
    }

    if (mode & 48) {
        int isK = (mode & 32) != 0;
#pragma unroll
        for (int mt = 0; mt < MT; mt++) {
#pragma unroll
            for (int half = 0; half < 2; half++) {
                int r = bm + m0w + mt * 16 + (lane >> 2) + half * 8;
                if (r >= M) continue;
                int b = r / 196, n = r % 196;
#pragma unroll
                for (int nt = 0; nt < NT; nt++) {
                    int col = bn + n0w + nt * 8 + ((lane & 3) << 1);
                    int h = col / 96, d = col - h * 96;
                    float v0 = acc[mt][nt][half * 2]     + bias[col];
                    float v1 = acc[mt][nt][half * 2 + 1] + bias[col + 1];
                    bf16 h0 = __float2bfloat16(v0), h1 = __float2bfloat16(v1);
                    __nv_bfloat162 hh = __halves2bfloat162(h0, h1);
                    __nv_bfloat162 ll = __halves2bfloat162(
                        __float2bfloat16(v0 - __bfloat162float(h0)),
                        __float2bfloat16(v1 - __bfloat162float(h1)));
                    uint32_t* qp = (uint32_t*)(outAug +
                        ((size_t)((b << 3) + h) * 196 + n) * 384);
                    int di = d >> 1;
                    qp[di] = *(uint32_t*)&hh;
                    if (isK) { qp[64 + di] = *(uint32_t*)&ll; qp[128 + di] = *(uint32_t*)&hh; }
                    else     { qp[64 + di] = *(uint32_t*)&hh; qp[128 + di] = *(uint32_t*)&ll; }
                }
            }
        }
        return;
    }

#pragma unroll
    for (int mt = 0; mt < MT; mt++) {
        int r0 = bm + m0w + mt * 16 + (lane >> 2);
        int r1 = r0 + 8;
#pragma unroll
        for (int nt = 0; nt < NT; nt++) {
            int col = bn + n0w + nt * 8 + ((lane & 3) << 1);
            if (r0 < M) {
                int bb = (mode & 8) ? (r0 / 196) * N : 0;
                float v0 = acc[mt][nt][0] + bias[bb + col];
                float v1 = acc[mt][nt][1] + bias[bb + col + 1];
                if (mode & 1) { v0 = gelu_exact(v0); v1 = gelu_exact(v1); }
                if (mode & 2) *(float2*)(out + (size_t)r0 * N + col) = make_float2(v0, v1);
                if (mode & 4) aug_store(outAug, (size_t)r0 * 3 * N, N, col, v0, v1);
            }
            if (r1 < M) {
                int bb = (mode & 8) ? (r1 / 196) * N : 0;
                float v2 = acc[mt][nt][2] + bias[bb + col];
                float v3 = acc[mt][nt][3] + bias[bb + col + 1];
                if (mode & 1) { v2 = gelu_exact(v2); v3 = gelu_exact(v3); }
                if (mode & 2) *(float2*)(out + (size_t)r1 * N + col) = make_float2(v2, v3);
                if (mode & 4) aug_store(outAug, (size_t)r1 * 3 * N, N, col, v2, v3);
            }
        }
    }
}

// ==================== batched aug GEMM for attention (R13 proven) ====================
__global__ __launch_bounds__(256, 2) void gemm_bat(
    const bf16* __restrict__ Aall, const bf16* __restrict__ Ball,
    uint16_t* __restrict__ oT3, float* __restrict__ gateSum,
    uint16_t* __restrict__ cAug, int MA, int NB, int K3, int epi)
{
    constexpr int BM = 128, BN = 128, MT = 4, NT = 4;
    constexpr int A_BYTES = BM * 128;
    constexpr int STG = (BM + BN) * 128;
    extern __shared__ __align__(1024) char smem[];
    uint32_t sb = smem_u32(smem);
    int tid = threadIdx.x, wid = tid >> 5, lane = tid & 31;
    int bz = blockIdx.z;
    const bf16* A = Aall + (size_t)bz * MA * K3;
    const bf16* Bw = Ball + (size_t)bz * NB * K3;
    int bm = blockIdx.y * BM, bn = blockIdx.x * BN;
    int m0w = (wid & 1) * 64;
    int n0w = (wid >> 1) * 32;
    int NC = K3 >> 6;

    auto load_stage = [&](int c) {
        uint32_t stage = sb + (c % GS) * STG;
        int k0 = c << 6;
#pragma unroll
        for (int g0 = 0; g0 < (BM + BN) * 8; g0 += 256) {
            int g = g0 + tid;
            int isB = (g >= BM * 8);
            int q = isB ? (g - BM * 8) : g;
            int row = q >> 3, c16 = q & 7;
            uint32_t dst = stage + (isB ? A_BYTES : 0) + swz((row << 7) + (c16 << 4));
            const bf16* src;
            int pred;
            if (!isB) {
                int gr = bm + row; pred = gr < MA;
                src = A + (size_t)(pred ? gr : 0) * K3 + k0 + (c16 << 3);
            } else {
                int gr = bn + row; pred = gr < NB;
                src = Bw + (size_t)(pred ? gr : 0) * K3 + k0 + (c16 << 3);
            }
            cp16(dst, src, pred);
        }
        asm volatile("cp.async.commit_group;" ::: "memory");
    };

    float acc[MT][NT][4];
#pragma unroll
    for (int mt = 0; mt < MT; mt++)
#pragma unroll
        for (int nt = 0; nt < NT; nt++)
#pragma unroll
            for (int i = 0; i < 4; i++) acc[mt][nt][i] = 0.f;

    load_stage(0);
    load_stage(1);

    for (int c = 0; c < NC; c++) {
        if (c == NC - 1) asm volatile("cp.async.wait_group 0;" ::: "memory");
        else             asm volatile("cp.async.wait_group 1;" ::: "memory");
        __syncthreads();
        if (c + 2 < NC) load_stage(c + 2);

        uint32_t sA = sb + (c % GS) * STG;
        uint32_t sB = sA + A_BYTES;
#pragma unroll
        for (int ks = 0; ks < 4; ks++) {
            uint32_t a[MT][4], bfr[NT / 2][4];
#pragma unroll
            for (int mt = 0; mt < MT; mt++) {
                int row = m0w + mt * 16 + (lane & 15);
                int ch = ks * 2 + (lane >> 4);
                uint32_t ad = sA + swz((uint32_t)(row << 7) + (ch << 4));
                LDSM4(a[mt][0], a[mt][1], a[mt][2], a[mt][3], ad);
            }
#pragma unroll
            for (int bp = 0; bp < NT / 2; bp++) {
                int row = n0w + bp * 16 + (lane & 7) + ((lane & 16) >> 1);
                int ch = ks * 2 + ((lane & 8) >> 3);
                uint32_t ad = sB + swz((uint32_t)(row << 7) + (ch << 4));
                LDSM4(bfr[bp][0], bfr[bp][1], bfr[bp][2], bfr[bp][3], ad);
            }
#pragma unroll
            for (int mt = 0; mt < MT; mt++)
#pragma unroll
                for (int nt = 0; nt < NT; nt++)
                    MMA16816(acc[mt][nt], a[mt],
                             bfr[nt >> 1][(nt & 1) * 2], bfr[nt >> 1][(nt & 1) * 2 + 1]);
        }
    }

    int bb = bz >> 3, hh = bz & 7;
    if (epi == 0) {
#pragma unroll
        for (int nt = 0; nt < NT; nt++) {
            int col = bn + n0w + nt * 8 + ((lane & 3) << 1);
            float g0 = 0.f, g1 = 0.f;
#pragma unroll
            for (int mt = 0; mt < MT; mt++) {
                int r0 = bm + m0w + mt * 16 + (lane >> 2);
                int r1 = r0 + 8;
                float v[4];
                v[0] = 1.f / (1.f + expf(-acc[mt][nt][0] * SCALE_));
                v[1] = 1.f / (1.f + expf(-acc[mt][nt][1] * SCALE_));
                v[2] = 1.f / (1.f + expf(-acc[mt][nt][2] * SCALE_));
                v[3] = 1.f / (1.f + expf(-acc[mt][nt][3] * SCALE_));
#pragma unroll
                for (int i = 0; i < 4; i++) {
                    int n = (i < 2) ? r0 : r1;
                    int m = col + (i & 1);
                    if (n < 196 && m < 196) {
                        float vv = v[i];
                        bf16 h = __float2bfloat16(vv);
                        bf16 l = __float2bfloat16(vv - __bfloat162float(h));
                        size_t base = ((size_t)bz * 196 + m) * 768;
                        oT3[base + n]       = *(uint16_t*)&h;
                        oT3[base + 256 + n] = *(uint16_t*)&h;
                        oT3[base + 512 + n] = *(uint16_t*)&l;
                        if (i & 1) g1 += vv; else g0 += vv;
                    }
                }
            }
            if (col < 196)     atomicAdd(gateSum + (size_t)bz * 196 + col, g0);
            if (col + 1 < 196) atomicAdd(gateSum + (size_t)bz * 196 + col + 1, g1);
        }
    } else {
#pragma unroll
        for (int mt = 0; mt < MT; mt++) {
            int r0 = bm + m0w + mt * 16 + (lane >> 2);
            int r1 = r0 + 8;
#pragma unroll
            for (int nt = 0; nt < NT; nt++) {
                int col = bn + n0w + nt * 8 + ((lane & 3) << 1);
                if (col + 1 < 96) {
                    if (r0 < 196)
                        aug_store(cAug, (size_t)(bb*196 + r0) * 3 * C_, C_, hh*96 + col,
                                  acc[mt][nt][0], acc[mt][nt][1]);
                    if (r1 < 196)
                        aug_store(cAug, (size_t)(bb*196 + r1) * 3 * C_, C_, hh*96 + col,
                                  acc[mt][nt][2], acc[mt][nt][3]);
                }
            }
        }
    }
}

// ==================== combined weight split ====================
struct WS8 {
    const float* src[8];
    uint16_t* dst[8];
    int K[8];
    int N[8];
};

__global__ void wsplitAll(WS8 p)
{
    int id = blockIdx.z;
    int K = p.K[id], N = p.N[id];
    int n0 = blockIdx.x * 32, k0 = blockIdx.y * 32;
    if (n0 >= N || k0 >= K) return;
    const float* w = p.src[id];
    uint16_t* aug = p.dst[id];
    __shared__ float t[32][33];
    int tx = threadIdx.x, ty = threadIdx.y;
#pragma unroll
    for (int j = 0; j < 4; j++)
        t[ty + 8 * j][tx] = w[(size_t)(k0 + ty + 8 * j) * N + n0 + tx];
    __syncthreads();
#pragma unroll
    for (int j = 0; j < 4; j++) {
        float v = t[tx][ty + 8 * j];
        int n = n0 + ty + 8 * j, k = k0 + tx;
        bf16 h = __float2bfloat16(v);
        bf16 l = __float2bfloat16(v - __bfloat162float(h));
        size_t base = (size_t)n * 3 * K;
        *(bf16*)(aug + base + k)         = h;
        *(bf16*)(aug + base + K + k)     = l;
        *(bf16*)(aug + base + 2 * K + k) = h;
    }
}

// ==================== pack_cgT ====================
__global__ void pack_cgT(const float* __restrict__ cg, uint16_t* __restrict__ dst)
{
    __shared__ float t[32][33];
    int bh = blockIdx.z, d0 = blockIdx.x * 32, n0 = blockIdx.y * 32;
    int b = bh >> 3, h = bh & 7;
    int tx = threadIdx.x, ty = threadIdx.y;
#pragma unroll
    for (int j = 0; j < 4; j++) {
        int n = n0 + ty + 8 * j;
        t[ty + 8 * j][tx] = (n < 196) ? cg[((size_t)b*196 + n)*768 + h*96 + d0 + tx] : 0.f;
    }
    __syncthreads();
#pragma unroll
    for (int j = 0; j < 4; j++) {
        int d = d0 + ty + 8 * j, n = n0 + tx;
        float v = t[tx][ty + 8 * j];
        bf16 hv = __float2bfloat16(v);
        bf16 lv = __float2bfloat16(v - __bfloat162float(hv));
        size_t base = ((size_t)bh*96 + d) * 768;
        dst[base + n]       = *(uint16_t*)&hv;
        dst[base + 256 + n] = *(uint16_t*)&lv;
        dst[base + 512 + n] = *(uint16_t*)&hv;
    }
}

// ==================== elementwise kernels ====================
__global__ __launch_bounds__(256) void ln_kernel(
    const float* __restrict__ x, const float* __restrict__ w,
    const float* __restrict__ b, float* __restrict__ y, uint16_t* __restrict__ xA)
{
    int row = blockIdx.x;
    int bb = row / (T_ * N_);
    int t  = (row / N_) % T_;
    int n  = row % N_;
    size_t xrow = ((size_t)(t * B_ + bb) * N_ + n) * 3 * C_;
    const float* xr = x + (size_t)row * C_;
    float v[3], s = 0.f, s2 = 0.f;
#pragma unroll
    for (int i = 0; i < 3; i++) { v[i] = xr[threadIdx.x + i*256]; s += v[i]; s2 += v[i]*v[i]; }
    __shared__ float red[18];
#pragma unroll
    for (int off = 16; off; off >>= 1) {
        s  += __shfl_down_sync(0xffffffffu, s, off);
        s2 += __shfl_down_sync(0xffffffffu, s2, off);
    }
    int wid = threadIdx.x >> 5, lane = threadIdx.x & 31;
    if (lane == 0) { red[wid] = s; red[8+wid] = s2; }
    __syncthreads();
    if (threadIdx.x == 0) {
        float ts = 0.f, ts2 = 0.f;
        for (int i = 0; i < 8; i++) { ts += red[i]; ts2 += red[8+i]; }
        red[16] = ts; red[17] = ts2;
    }
    __syncthreads();
    float mean = red[16] * (1.0f/C_);
    float inv  = rsqrtf(red[17] * (1.0f/C_) - mean*mean + 1e-5f);
    float* yr = y + (size_t)row * C_;
#pragma unroll
    for (int i = 0; i < 3; i++) {
        int c = threadIdx.x + i*256;
        float o = (v[i] - mean) * inv * w[c] + b[c];
        yr[c] = o;
        bf16 h = __float2bfloat16(o);
        xA[xrow + c]         = *(uint16_t*)&h;
        xA[xrow + C_ + c]    = *(uint16_t*)&h;
        bf16 l = __float2bfloat16(o - __bfloat162float(h));
        xA[xrow + 2*C_ + c]  = *(uint16_t*)&l;
    }
}

__global__ void ap_kernel(const float* __restrict__ mem, float* __restrict__ ap)
{
    int idx = blockIdx.x * 256 + threadIdx.x;
    if (idx >= B_*C_) return;
    int z = blockIdx.y;
    int b = idx / C_, c = idx % C_;
    float s = 0.f;
    const float* p = mem + (size_t)b*MEM_*C_ + (size_t)(z * 49)*C_ + c;
#pragma unroll 7
    for (int m = 0; m < 49; m++) s += p[(size_t)m*C_];
    atomicAdd(&ap[idx], s * (1.0f/MEM_));
}

__global__ __launch_bounds__(128) void apw2(
    const float* __restrict__ ap, const float* __restrict__ c_w1,
    const float* __restrict__ c_b1, float* __restrict__ bias2)
{
    int b = blockIdx.y;
    int j = blockIdx.x * 128 + threadIdx.x;
    __shared__ float aps[768];
    for (int k = threadIdx.x; k < 768; k += 128) aps[k] = ap[b * 768 + k];
    __syncthreads();
    const float* wp = c_w1 + (size_t)768 * HID_ + j;
    float a0 = 0.f, a1 = 0.f, a2 = 0.f, a3 = 0.f;
#pragma unroll 8
    for (int k = 0; k < 768; k += 4) {
        a0 = fmaf(aps[k],     wp[(size_t)(k)     * HID_], a0);
        a1 = fmaf(aps[k + 1], wp[(size_t)(k + 1) * HID_], a1);
        a2 = fmaf(aps[k + 2], wp[(size_t)(k + 2) * HID_], a2);
        a3 = fmaf(aps[k + 3], wp[(size_t)(k + 3) * HID_], a3);
    }
    bias2[b * HID_ + j] = c_b1[j] + ((a0 + a1) + (a2 + a3));
}

__global__ __launch_bounds__(256) void final_kernel(
    const float* __restrict__ c2, const float* __restrict__ c2b,
    const float* __restrict__ gateSum, const float* __restrict__ memh,
    const float* __restrict__ w, const float* __restrict__ bb,
    float* __restrict__ y, uint16_t* __restrict__ aug)
{
    int row = blockIdx.x;
    int b = row / MEM_, m = row % MEM_;
    float v[3], s = 0.f, s2 = 0.f;
#pragma unroll
    for (int i = 0; i < 3; i++) {
        int c = threadIdx.x + i*256;
        float g = 1.0f - gateSum[(b*H_ + (c/D_))*MEM_ + m] * (1.0f / N_);
        v[i] = c2[(size_t)row*C_ + c] + c2b[(size_t)row*C_ + c] + g * memh[(size_t)row*C_ + c];
        s += v[i]; s2 += v[i]*v[i];
    }
    __shared__ float red[18];
#pragma unroll
    for (int off = 16; off; off >>= 1) {
        s  += __shfl_down_sync(0xffffffffu, s, off);
        s2 += __shfl_down_sync(0xffffffffu, s2, off);
    }
    int wid = threadIdx.x >> 5, lane = threadIdx.x & 31;
    if (lane == 0) { red[wid] = s; red[8+wid] = s2; }
    __syncthreads();
    if (threadIdx.x == 0) {
        float ts = 0.f, ts2 = 0.f;
        for (int i = 0; i < 8; i++) { ts += red[i]; ts2 += red[8+i]; }
        red[16] = ts; red[17] = ts2;
    }
    __syncthreads();
    float mean = red[16] * (1.0f/C_);
    float inv  = rsqrtf(red[17] * (1.0f/C_) - mean*mean + 1e-5f);
    float* yr = y + (size_t)row * C_;
    size_t base = (size_t)row * 3 * C_;
#pragma unroll
    for (int i = 0; i < 3; i++) {
        int c = threadIdx.x + i*256;
        float o = (v[i] - mean) * inv * w[c] + bb[c];
        yr[c] = o;
        bf16 h = __float2bfloat16(o);
        aug[base + c]        = *(uint16_t*)&h;
        aug[base + C_ + c]   = *(uint16_t*)&h;
        bf16 l = __float2bfloat16(o - __bfloat162float(h));
        aug[base + 2*C_ + c] = *(uint16_t*)&l;
    }
}

__global__ void initmem_kernel(const float* __restrict__ x, float* __restrict__ mem,
                               uint16_t* __restrict__ aug)
{
    int idx = blockIdx.x * 256 + threadIdx.x;
    if (idx >= B_*MEM_*C_/2) return;
    int row = idx / (C_/2), jp = (idx % (C_/2)) * 2;
    int b = row / MEM_, r = row % MEM_;
    float2 v = *(const float2*)(x + (size_t)b*T_*N_*C_ + (size_t)r*C_ + jp);
    *(float2*)(mem + (size_t)row*C_ + jp) = v;
    aug_store(aug, (size_t)row * 3 * C_, C_, jp, v.x, v.y);
}

// ==================== host orchestration ====================
#define SMEM_128 (GS * (128 + 128) * 128)   // 98304
#define SMEM_SM  (GS * (64 + 128) * 128)    // 73728

static void gemm_big(const uint16_t* a, const uint16_t* w, const float* bias,
                     float* out, uint16_t* outAug, int M, int N, int K, int mode,
                     cudaStream_t st)
{
    dim3 g(N / 128, (M + 127) / 128);
    gemm_mma<128, 128, 4, 4><<<g, 256, SMEM_128, st>>>(
        (const bf16*)a, (const bf16*)w, bias, out, outAug, M, N, 3 * K, 3 * K, mode);
}
static void gemm_sm(const uint16_t* a, const uint16_t* w, const float* bias,
                    float* out, uint16_t* outAug, int M, int N, int K, int mode,
                    cudaStream_t st)
{
    dim3 g(N / 128, (M + 63) / 64);
    gemm_mma<64, 128, 2, 4><<<g, 256, SMEM_SM, st>>>(
        (const bf16*)a, (const bf16*)w, bias, out, outAug, M, N, 3 * K, 3 * K, mode);
}
// split-K half: loop-count K3h, full row stride ldK; caller offsets pointers
static void gemm_sm_k(const uint16_t* a, const uint16_t* w, const float* bias,
                      float* out, int M, int N, int K3h, int ldK, int mode,
                      cudaStream_t st)
{
    dim3 g(N / 128, (M + 63) / 64);
    gemm_mma<64, 128, 2, 4><<<g, 256, SMEM_SM, st>>>(
        (const bf16*)a, (const bf16*)w, bias, out, nullptr, M, N, K3h, ldK, mode);
}

extern "C" void kernel_launch(void* const* d_in, const int* in_sizes, int n_in,
                              void* d_out, int out_size)
{
    const float* cur_fea = (const float*)d_in[0];
    const float* n1w = (const float*)d_in[1];
    const float* n1b = (const float*)d_in[2];
    const float* n2w = (const float*)d_in[3];
    const float* n2b = (const float*)d_in[4];
    const float* c_w1 = (const float*)d_in[5];  const float* c_b1 = (const float*)d_in[6];
    const float* c_w2 = (const float*)d_in[7];  const float* c_b2 = (const float*)d_in[8];
    const float* m_w1 = (const float*)d_in[9];  const float* m_b1 = (const float*)d_in[10];
    const float* m_w2 = (const float*)d_in[11]; const float* m_b2 = (const float*)d_in[12];
    const float* p_w1 = (const float*)d_in[13]; const float* p_b1 = (const float*)d_in[14];
    const float* p_w2 = (const float*)d_in[15]; const float* p_b2 = (const float*)d_in[16];
    const float* q_w = (const float*)d_in[17];  const float* q_b = (const float*)d_in[18];
    const float* k_w = (const float*)d_in[19];  const float* k_b = (const float*)d_in[20];

    cudaFuncSetAttribute((const void*)gemm_mma<128, 128, 4, 4>,
                         cudaFuncAttributeMaxDynamicSharedMemorySize, SMEM_128);
    cudaFuncSetAttribute((const void*)gemm_mma<64, 128, 2, 4>,
                         cudaFuncAttributeMaxDynamicSharedMemorySize, SMEM_SM);
    cudaFuncSetAttribute((const void*)gemm_bat,
                         cudaFuncAttributeMaxDynamicSharedMemorySize, SMEM_128);

    static cudaStream_t sS = nullptr;
    static cudaEvent_t eA, eK, eCG, eS2, eP, eP2;
    if (!sS) {
        cudaStreamCreateWithFlags(&sS, cudaStreamNonBlocking);
        cudaEventCreateWithFlags(&eA,  cudaEventDisableTiming);
        cudaEventCreateWithFlags(&eK,  cudaEventDisableTiming);
        cudaEventCreateWithFlags(&eCG, cudaEventDisableTiming);
        cudaEventCreateWithFlags(&eS2, cudaEventDisableTiming);
        cudaEventCreateWithFlags(&eP,  cudaEventDisableTiming);
        cudaEventCreateWithFlags(&eP2, cudaEventDisableTiming);
    }

    float *x, *cg, *memh, *c2, *c2b, *gate, *ap, *bias2, *zero, *memA, *memB;
    cudaGetSymbolAddress((void**)&x, g_x);       cudaGetSymbolAddress((void**)&cg, g_cg);
    cudaGetSymbolAddress((void**)&memh, g_memh);
    cudaGetSymbolAddress((void**)&c2, g_c2);     cudaGetSymbolAddress((void**)&c2b, g_c2b);
    cudaGetSymbolAddress((void**)&gate, g_gate);
    cudaGetSymbolAddress((void**)&ap, g_ap);     cudaGetSymbolAddress((void**)&bias2, g_bias2);
    cudaGetSymbolAddress((void**)&zero, g_zero);
    cudaGetSymbolAddress((void**)&memA, g_memA); cudaGetSymbolAddress((void**)&memB, g_memB);

    uint16_t *xA, *hidCA, *hidMA, *cgA, *cA, *memAg, *Q3, *K3, *oT3, *cgT3;
    uint16_t *wc1, *wc2, *wm1, *wm2, *wp1, *wp2, *wq, *wk;
    cudaGetSymbolAddress((void**)&xA, g_xA);
    cudaGetSymbolAddress((void**)&hidCA, g_hidCA);
    cudaGetSymbolAddress((void**)&hidMA, g_hidMA);
    cudaGetSymbolAddress((void**)&cgA, g_cgA);   cudaGetSymbolAddress((void**)&cA, g_cA);
    cudaGetSymbolAddress((void**)&memAg, g_memAg);
    cudaGetSymbolAddress((void**)&Q3, g_Q3);     cudaGetSymbolAddress((void**)&K3, g_K3);
    cudaGetSymbolAddress((void**)&oT3, g_oT3);   cudaGetSymbolAddress((void**)&cgT3, g_cgT3);
    cudaGetSymbolAddress((void**)&wc1, g_wc1);   cudaGetSymbolAddress((void**)&wc2, g_wc2);
    cudaGetSymbolAddress((void**)&wm1, g_wm1);   cudaGetSymbolAddress((void**)&wm2, g_wm2);
    cudaGetSymbolAddress((void**)&wp1, g_wp1);   cudaGetSymbolAddress((void**)&wp2, g_wp2);
    cudaGetSymbolAddress((void**)&wq, g_wq);     cudaGetSymbolAddress((void**)&wk, g_wk);

    WS8 ws;
    ws.src[0] = c_w1; ws.dst[0] = wc1; ws.K[0] = C_;   ws.N[0] = HID_;
    ws.src[1] = c_w2; ws.dst[1] = wc2; ws.K[1] = HID_; ws.N[1] = C_;
    ws.src[2] = m_w1; ws.dst[2] = wm1; ws.K[2] = C_;   ws.N[2] = HID_;
    ws.src[3] = m_w2; ws.dst[3] = wm2; ws.K[3] = HID_; ws.N[3] = C_;
    ws.src[4] = p_w1; ws.dst[4] = wp1; ws.K[4] = C_;   ws.N[4] = HID_;
    ws.src[5] = p_w2; ws.dst[5] = wp2; ws.K[5] = HID_; ws.N[5] = C_;
    ws.src[6] = q_w;  ws.dst[6] = wq;  ws.K[6] = C_;   ws.N[6] = C_;
    ws.src[7] = k_w;  ws.dst[7] = wk;  ws.K[7] = C_;   ws.N[7] = C_;
    dim3 wb(32, 8);
    wsplitAll<<<dim3(96, 96, 8), wb>>>(ws);

    ln_kernel<<<B_*T_*N_, 256>>>(cur_fea, n1w, n1b, x, xA);
    initmem_kernel<<<(B_*MEM_*C_/2 + 255)/256, 256>>>(x, memA, memAg);

    float* mcur = memA;
    float* mnxt = memB;

    for (int t = 1; t < T_; t++) {
        cudaEventRecord(eA, 0);
        cudaStreamWaitEvent(sS, eA, 0);

        // ---- stream S: m-chain (k first to release eK early) ----
        gemm_sm (memAg, wk, k_b, nullptr, K3, ROWS_, C_, C_, 32, sS);          // k -> K3
        cudaEventRecord(eK, sS);
        gemm_big(memAg, wm1, m_b1, nullptr, hidMA, ROWS_, HID_, C_, 1|4, sS);  // fc1_m
        gemm_sm (hidMA, wm2, m_b2, memh, nullptr, ROWS_, C_, HID_, 2, sS);     // fc2_m

        // ---- legacy stream L: c-chain ----
        cudaMemsetAsync(ap, 0, B_*C_*sizeof(float), 0);
        ap_kernel<<<dim3((B_*C_ + 255)/256, 4), 256>>>(mcur, ap);
        apw2<<<dim3(HID_/128, B_), 128>>>(ap, c_w1, c_b1, bias2);
        const uint16_t* feaA = xA + (size_t)t * ROWS_ * 3 * C_;
        gemm_big(feaA, wc1, bias2, nullptr, hidCA, ROWS_, HID_, C_, 1|4|8, 0); // fc1_c
        gemm_sm (hidCA, wc2, c_b2, cg, cgA, ROWS_, C_, HID_, 2|4, 0);          // fc2_c
        cudaEventRecord(eCG, 0);
        cudaStreamWaitEvent(sS, eCG, 0);
        pack_cgT<<<dim3(3, 8, 64), wb, 0, sS>>>(cg, cgT3);                     // on S
        cudaEventRecord(eS2, sS);

        gemm_sm (cgA, wq, q_b, nullptr, Q3, ROWS_, C_, C_, 16, 0);             // q -> Q3
        cudaMemsetAsync(gate, 0, B_*H_*MEM_*sizeof(float), 0);
        cudaStreamWaitEvent(0, eK, 0);
        gemm_bat<<<dim3(2, 2, 64), 256, SMEM_128>>>(
            (const bf16*)Q3, (const bf16*)K3, oT3, gate, nullptr, 196, 196, 384, 0);
        cudaStreamWaitEvent(0, eS2, 0);
        gemm_bat<<<dim3(1, 2, 64), 256, SMEM_128>>>(
            (const bf16*)oT3, (const bf16*)cgT3, nullptr, nullptr, cA, 196, 96, 768, 1);

        gemm_big(cA, wp1, p_b1, nullptr, hidCA, ROWS_, HID_, C_, 1|4, 0);      // fc1_p
        cudaEventRecord(eP, 0);
        cudaStreamWaitEvent(sS, eP, 0);
        // fc2_p split-K2: half1 on L (bias), half2 on S (zero bias)
        gemm_sm_k(hidCA, wp2, p_b2, c2, ROWS_, C_, 4608, 9216, 2, 0);
        gemm_sm_k(hidCA + 4608, wp2 + 4608, zero, c2b, ROWS_, C_, 4608, 9216, 2, sS);
        cudaEventRecord(eP2, sS);
        cudaStreamWaitEvent(0, eP2, 0);

        float* dst = (t == T_ - 1) ? (float*)d_out : mnxt;
        final_kernel<<<B_*MEM_, 256>>>(c2, c2b, gate, memh, n2w, n2b, dst, memAg);

        float* tmp = mcur; mcur = mnxt; mnxt = tmp;
    }
}

// round 16
// speedup vs baseline: 1.0227x; 1.0227x over previous
#include <cuda_runtime.h>
#include <cuda_bf16.h>
#include <math.h>
#include <stdint.h>

#define B_   8
#define T_   16
#define N_   196
#define C_   768
#define H_   8
#define D_   96
#define MEM_ 196
#define HID_ 3072
#define ROWS_ 1568
#define SCALE_ 0.1020620726159657f

typedef __nv_bfloat16 bf16;

// ---------------- fp32 scratch ----------------
__device__ __align__(256) float g_x   [B_*T_*N_*C_];
__device__ __align__(256) float g_cg  [ROWS_*C_];
__device__ __align__(256) float g_memh[ROWS_*C_];
__device__ __align__(256) float g_c2  [ROWS_*C_];
__device__ __align__(256) float g_gate[B_*H_*MEM_];
__device__ __align__(256) float g_ap  [B_*C_];
__device__ __align__(256) float g_bias2[B_*HID_];
__device__ __align__(256) float g_memA[ROWS_*C_];
__device__ __align__(256) float g_memB[ROWS_*C_];

// ---------------- augmented bf16 activations ----------------
__device__ __align__(256) uint16_t g_xA  [T_*B_*N_*3*C_];
__device__ __align__(256) uint16_t g_hidCA[ROWS_*3*HID_];
__device__ __align__(256) uint16_t g_hidMA[ROWS_*3*HID_];
__device__ __align__(256) uint16_t g_cgA [ROWS_*3*C_];
__device__ __align__(256) uint16_t g_cA  [ROWS_*3*C_];
__device__ __align__(256) uint16_t g_memAg[ROWS_*3*C_];

// attention aug operands (zero-init; pads never written)
__device__ __align__(256) uint16_t g_Q3 [64*196*384];
__device__ __align__(256) uint16_t g_K3 [64*196*384];
__device__ __align__(256) uint16_t g_oT3[64*196*768];
__device__ __align__(256) uint16_t g_cgT3[64*96*768];

// weights augmented [N][3K] = [hi|lo|hi]
__device__ __align__(256) uint16_t g_wc1[HID_*3*C_];
__device__ __align__(256) uint16_t g_wc2[C_*3*HID_];
__device__ __align__(256) uint16_t g_wm1[HID_*3*C_];
__device__ __align__(256) uint16_t g_wm2[C_*3*HID_];
__device__ __align__(256) uint16_t g_wp1[HID_*3*C_];
__device__ __align__(256) uint16_t g_wp2[C_*3*HID_];
__device__ __align__(256) uint16_t g_wq [C_*3*C_];
__device__ __align__(256) uint16_t g_wk [C_*3*C_];

__device__ __forceinline__ float gelu_exact(float x) {
    return 0.5f * x * (1.0f + erff(x * 0.70710678118654752f));
}
__device__ __forceinline__ uint32_t smem_u32(const void* p) {
    uint32_t a;
    asm("{ .reg .u64 t; cvta.to.shared.u64 t, %1; cvt.u32.u64 %0, t; }" : "=r"(a) : "l"(p));
    return a;
}
__device__ __forceinline__ void cp16(uint32_t dst, const void* src, int pred) {
    int sz = pred ? 16 : 0;
    asm volatile("cp.async.cg.shared.global [%0], [%1], 16, %2;" :: "r"(dst), "l"(src), "r"(sz) : "memory");
}
__device__ __forceinline__ uint32_t swz(uint32_t o) { return o ^ ((o >> 3) & 0x70); }

#define LDSM4(r0, r1, r2, r3, addr) \
    asm volatile("ldmatrix.sync.aligned.m8n8.x4.shared.b16 {%0,%1,%2,%3}, [%4];" \
        : "=r"(r0), "=r"(r1), "=r"(r2), "=r"(r3) : "r"(addr))

#define MMA16816(d, a, b0, b1) \
    asm volatile("mma.sync.aligned.m16n8k16.row.col.f32.bf16.bf16.f32 " \
        "{%0,%1,%2,%3}, {%4,%5,%6,%7}, {%8,%9}, {%0,%1,%2,%3};" \
        : "+f"((d)[0]), "+f"((d)[1]), "+f"((d)[2]), "+f"((d)[3]) \
        : "r"((a)[0]), "r"((a)[1]), "r"((a)[2]), "r"((a)[3]), "r"(b0), "r"(b1))

__device__ __forceinline__ void aug_store(uint16_t* aug, size_t base, int Ncols, int col,
                                          float v0, float v1)
{
    bf16 h0 = __float2bfloat16(v0), h1 = __float2bfloat16(v1);
    __nv_bfloat162 hh = __halves2bfloat162(h0, h1);
    __nv_bfloat162 ll = __halves2bfloat162(__float2bfloat16(v0 - __bfloat162float(h0)),
                                           __float2bfloat16(v1 - __bfloat162float(h1)));
    *(uint32_t*)(aug + base + col)             = *(uint32_t*)&hh;
    *(uint32_t*)(aug + base + Ncols + col)     = *(uint32_t*)&hh;
    *(uint32_t*)(aug + base + 2 * Ncols + col) = *(uint32_t*)&ll;
}

// ==================== GEMM (proven core; GS templated) ====================
// mode bits: 1=gelu, 2=fp32 out, 4=aug out, 8=per-batch bias, 16=Q3 aug, 32=K3 aug
template<int BM, int BN, int MT, int NT, int GS_>
__global__ __launch_bounds__(256, 2) void gemm_mma(
    const bf16* __restrict__ A, const bf16* __restrict__ Bw,
    const float* __restrict__ bias, float* __restrict__ out,
    uint16_t* __restrict__ outAug, int M, int N, int K3, int mode)
{
    constexpr int A_BYTES = BM * 128;
    constexpr int STG = (BM + BN) * 128;
    extern __shared__ __align__(1024) char smem[];
    uint32_t sb = smem_u32(smem);
    int tid = threadIdx.x, wid = tid >> 5, lane = tid & 31;
    int bm = blockIdx.y * BM, bn = blockIdx.x * BN;
    int m0w = (wid & 1) * (MT * 16);
    int n0w = (wid >> 1) * (NT * 8);
    int NC = K3 >> 6;

    auto load_stage = [&](int c) {
        uint32_t stage = sb + (c % GS_) * STG;
        int k0 = c << 6;
        constexpr int TOT = (BM + BN) * 8;
#pragma unroll
        for (int g0 = 0; g0 < TOT; g0 += 256) {
            int g = g0 + tid;
            int isB = (g >= BM * 8);
            int q = isB ? (g - BM * 8) : g;
            int row = q >> 3, c16 = q & 7;
            uint32_t dst = stage + (isB ? A_BYTES : 0) + swz((row << 7) + (c16 << 4));
            const bf16* src;
            int pred = 1;
            if (!isB) {
                int gr = bm + row; pred = gr < M;
                src = A + (size_t)(pred ? gr : 0) * K3 + k0 + (c16 << 3);
            } else {
                int gr = bn + row;
                src = Bw + (size_t)gr * K3 + k0 + (c16 << 3);
            }
            cp16(dst, src, pred);
        }
        asm volatile("cp.async.commit_group;" ::: "memory");
    };

    float acc[MT][NT][4];
#pragma unroll
    for (int mt = 0; mt < MT; mt++)
#pragma unroll
        for (int nt = 0; nt < NT; nt++)
#pragma unroll
            for (int i = 0; i < 4; i++) acc[mt][nt][i] = 0.f;

#pragma unroll
    for (int s = 0; s < GS_ - 1; s++)
        if (s < NC) load_stage(s);

    for (int c = 0; c < NC; c++) {
        int w = NC - c - 1;
        if (w > GS_ - 2) w = GS_ - 2;
        if (w == 0)      asm volatile("cp.async.wait_group 0;" ::: "memory");
        else if (w == 1) asm volatile("cp.async.wait_group 1;" ::: "memory");
        else             asm volatile("cp.async.wait_group 2;" ::: "memory");
        __syncthreads();
        if (c + GS_ - 1 < NC) load_stage(c + GS_ - 1);

        uint32_t sA = sb + (c % GS_) * STG;
        uint32_t sB = sA + A_BYTES;
#pragma unroll
        for (int ks = 0; ks < 4; ks++) {
            uint32_t a[MT][4], bfr[NT / 2][4];
#pragma unroll
            for (int mt = 0; mt < MT; mt++) {
                int row = m0w + mt * 16 + (lane & 15);
                int ch = ks * 2 + (lane >> 4);
                uint32_t ad = sA + swz((uint32_t)(row << 7) + (ch << 4));
                LDSM4(a[mt][0], a[mt][1], a[mt][2], a[mt][3], ad);
            }
#pragma unroll
            for (int bp = 0; bp < NT / 2; bp++) {
                int row = n0w + bp * 16 + (lane & 7) + ((lane & 16) >> 1);
                int ch = ks * 2 + ((lane & 8) >> 3);
                uint32_t ad = sB + swz((uint32_t)(row << 7) + (ch << 4));
                LDSM4(bfr[bp][0], bfr[bp][1], bfr[bp][2], bfr[bp][3], ad);
            }
#pragma unroll
            for (int mt = 0; mt < MT; mt++)
#pragma unroll
                for (int nt = 0; nt < NT; nt++)
                    MMA16816(acc[mt][nt], a[mt],
                             bfr[nt >> 1][(nt & 1) * 2], bfr[nt >> 1][(nt & 1) * 2 + 1]);
        }
    }

    if (mode & 48) {
        int isK = (mode & 32) != 0;
#pragma unroll
        for (int mt = 0; mt < MT; mt++) {
#pragma unroll
            for (int half = 0; half < 2; half++) {
                int r = bm + m0w + mt * 16 + (lane >> 2) + half * 8;
                if (r >= M) continue;
                int b = r / 196, n = r % 196;
#pragma unroll
                for (int nt = 0; nt < NT; nt++) {
                    int col = bn + n0w + nt * 8 + ((lane & 3) << 1);
                    int h = col / 96, d = col - h * 96;
                    float v0 = acc[mt][nt][half * 2]     + bias[col];
                    float v1 = acc[mt][nt][half * 2 + 1] + bias[col + 1];
                    bf16 h0 = __float2bfloat16(v0), h1 = __float2bfloat16(v1);
                    __nv_bfloat162 hh = __halves2bfloat162(h0, h1);
                    __nv_bfloat162 ll = __halves2bfloat162(
                        __float2bfloat16(v0 - __bfloat162float(h0)),
                        __float2bfloat16(v1 - __bfloat162float(h1)));
                    uint32_t* qp = (uint32_t*)(outAug +
                        ((size_t)((b << 3) + h) * 196 + n) * 384);
                    int di = d >> 1;
                    qp[di] = *(uint32_t*)&hh;
                    if (isK) { qp[64 + di] = *(uint32_t*)&ll; qp[128 + di] = *(uint32_t*)&hh; }
                    else     { qp[64 + di] = *(uint32_t*)&hh; qp[128 + di] = *(uint32_t*)&ll; }
                }
            }
        }
        return;
    }

#pragma unroll
    for (int mt = 0; mt < MT; mt++) {
        int r0 = bm + m0w + mt * 16 + (lane >> 2);
        int r1 = r0 + 8;
#pragma unroll
        for (int nt = 0; nt < NT; nt++) {
            int col = bn + n0w + nt * 8 + ((lane & 3) << 1);
            if (r0 < M) {
                int bb = (mode & 8) ? (r0 / 196) * N : 0;
                float v0 = acc[mt][nt][0] + bias[bb + col];
                float v1 = acc[mt][nt][1] + bias[bb + col + 1];
                if (mode & 1) { v0 = gelu_exact(v0); v1 = gelu_exact(v1); }
                if (mode & 2) *(float2*)(out + (size_t)r0 * N + col) = make_float2(v0, v1);
                if (mode & 4) aug_store(outAug, (size_t)r0 * 3 * N, N, col, v0, v1);
            }
            if (r1 < M) {
                int bb = (mode & 8) ? (r1 / 196) * N : 0;
                float v2 = acc[mt][nt][2] + bias[bb + col];
                float v3 = acc[mt][nt][3] + bias[bb + col + 1];
                if (mode & 1) { v2 = gelu_exact(v2); v3 = gelu_exact(v3); }
                if (mode & 2) *(float2*)(out + (size_t)r1 * N + col) = make_float2(v2, v3);
                if (mode & 4) aug_store(outAug, (size_t)r1 * 3 * N, N, col, v2, v3);
            }
        }
    }
}

// ==================== batched aug GEMM for attention (R13 proven, GS=3) ====================
#define GSB 3
__global__ __launch_bounds__(256, 2) void gemm_bat(
    const bf16* __restrict__ Aall, const bf16* __restrict__ Ball,
    uint16_t* __restrict__ oT3, float* __restrict__ gateSum,
    uint16_t* __restrict__ cAug, int MA, int NB, int K3, int epi)
{
    constexpr int BM = 128, BN = 128, MT = 4, NT = 4;
    constexpr int A_BYTES = BM * 128;
    constexpr int STG = (BM + BN) * 128;
    extern __shared__ __align__(1024) char smem[];
    uint32_t sb = smem_u32(smem);
    int tid = threadIdx.x, wid = tid >> 5, lane = tid & 31;
    int bz = blockIdx.z;
    const bf16* A = Aall + (size_t)bz * MA * K3;
    const bf16* Bw = Ball + (size_t)bz * NB * K3;
    int bm = blockIdx.y * BM, bn = blockIdx.x * BN;
    int m0w = (wid & 1) * 64;
    int n0w = (wid >> 1) * 32;
    int NC = K3 >> 6;

    auto load_stage = [&](int c) {
        uint32_t stage = sb + (c % GSB) * STG;
        int k0 = c << 6;
#pragma unroll
        for (int g0 = 0; g0 < (BM + BN) * 8; g0 += 256) {
            int g = g0 + tid;
            int isB = (g >= BM * 8);
            int q = isB ? (g - BM * 8) : g;
            int row = q >> 3, c16 = q & 7;
            uint32_t dst = stage + (isB ? A_BYTES : 0) + swz((row << 7) + (c16 << 4));
            const bf16* src;
            int pred;
            if (!isB) {
                int gr = bm + row; pred = gr < MA;
                src = A + (size_t)(pred ? gr : 0) * K3 + k0 + (c16 << 3);
            } else {
                int gr = bn + row; pred = gr < NB;
                src = Bw + (size_t)(pred ? gr : 0) * K3 + k0 + (c16 << 3);
            }
            cp16(dst, src, pred);
        }
        asm volatile("cp.async.commit_group;" ::: "memory");
    };

    float acc[MT][NT][4];
#pragma unroll
    for (int mt = 0; mt < MT; mt++)
#pragma unroll
        for (int nt = 0; nt < NT; nt++)
#pragma unroll
            for (int i = 0; i < 4; i++) acc[mt][nt][i] = 0.f;

    load_stage(0);
    load_stage(1);

    for (int c = 0; c < NC; c++) {
        if (c == NC - 1) asm volatile("cp.async.wait_group 0;" ::: "memory");
        else             asm volatile("cp.async.wait_group 1;" ::: "memory");
        __syncthreads();
        if (c + 2 < NC) load_stage(c + 2);

        uint32_t sA = sb + (c % GSB) * STG;
        uint32_t sB = sA + A_BYTES;
#pragma unroll
        for (int ks = 0; ks < 4; ks++) {
            uint32_t a[MT][4], bfr[NT / 2][4];
#pragma unroll
            for (int mt = 0; mt < MT; mt++) {
                int row = m0w + mt * 16 + (lane & 15);
                int ch = ks * 2 + (lane >> 4);
                uint32_t ad = sA + swz((uint32_t)(row << 7) + (ch << 4));
                LDSM4(a[mt][0], a[mt][1], a[mt][2], a[mt][3], ad);
            }
#pragma unroll
            for (int bp = 0; bp < NT / 2; bp++) {
                int row = n0w + bp * 16 + (lane & 7) + ((lane & 16) >> 1);
                int ch = ks * 2 + ((lane & 8) >> 3);
                uint32_t ad = sB + swz((uint32_t)(row << 7) + (ch << 4));
                LDSM4(bfr[bp][0], bfr[bp][1], bfr[bp][2], bfr[bp][3], ad);
            }
#pragma unroll
            for (int mt = 0; mt < MT; mt++)
#pragma unroll
                for (int nt = 0; nt < NT; nt++)
                    MMA16816(acc[mt][nt], a[mt],
                             bfr[nt >> 1][(nt & 1) * 2], bfr[nt >> 1][(nt & 1) * 2 + 1]);
        }
    }

    int bb = bz >> 3, hh = bz & 7;
    if (epi == 0) {
#pragma unroll
        for (int nt = 0; nt < NT; nt++) {
            int col = bn + n0w + nt * 8 + ((lane & 3) << 1);
            float g0 = 0.f, g1 = 0.f;
#pragma unroll
            for (int mt = 0; mt < MT; mt++) {
                int r0 = bm + m0w + mt * 16 + (lane >> 2);
                int r1 = r0 + 8;
                float v[4];
                v[0] = 1.f / (1.f + expf(-acc[mt][nt][0] * SCALE_));
                v[1] = 1.f / (1.f + expf(-acc[mt][nt][1] * SCALE_));
                v[2] = 1.f / (1.f + expf(-acc[mt][nt][2] * SCALE_));
                v[3] = 1.f / (1.f + expf(-acc[mt][nt][3] * SCALE_));
#pragma unroll
                for (int i = 0; i < 4; i++) {
                    int n = (i < 2) ? r0 : r1;
                    int m = col + (i & 1);
                    if (n < 196 && m < 196) {
                        float vv = v[i];
                        bf16 h = __float2bfloat16(vv);
                        bf16 l = __float2bfloat16(vv - __bfloat162float(h));
                        size_t base = ((size_t)bz * 196 + m) * 768;
                        oT3[base + n]       = *(uint16_t*)&h;
                        oT3[base + 256 + n] = *(uint16_t*)&h;
                        oT3[base + 512 + n] = *(uint16_t*)&l;
                        if (i & 1) g1 += vv; else g0 += vv;
                    }
                }
            }
            if (col < 196)     atomicAdd(gateSum + (size_t)bz * 196 + col, g0);
            if (col + 1 < 196) atomicAdd(gateSum + (size_t)bz * 196 + col + 1, g1);
        }
    } else {
#pragma unroll
        for (int mt = 0; mt < MT; mt++) {
            int r0 = bm + m0w + mt * 16 + (lane >> 2);
            int r1 = r0 + 8;
#pragma unroll
            for (int nt = 0; nt < NT; nt++) {
                int col = bn + n0w + nt * 8 + ((lane & 3) << 1);
                if (col + 1 < 96) {
                    if (r0 < 196)
                        aug_store(cAug, (size_t)(bb*196 + r0) * 3 * C_, C_, hh*96 + col,
                                  acc[mt][nt][0], acc[mt][nt][1]);
                    if (r1 < 196)
                        aug_store(cAug, (size_t)(bb*196 + r1) * 3 * C_, C_, hh*96 + col,
                                  acc[mt][nt][2], acc[mt][nt][3]);
                }
            }
        }
    }
}

// ==================== combined weight split ====================
struct WS8 {
    const float* src[8];
    uint16_t* dst[8];
    int K[8];
    int N[8];
};

__global__ void wsplitAll(WS8 p)
{
    int id = blockIdx.z;
    int K = p.K[id], N = p.N[id];
    int n0 = blockIdx.x * 32, k0 = blockIdx.y * 32;
    if (n0 >= N || k0 >= K) return;
    const float* w = p.src[id];
    uint16_t* aug = p.dst[id];
    __shared__ float t[32][33];
    int tx = threadIdx.x, ty = threadIdx.y;
#pragma unroll
    for (int j = 0; j < 4; j++)
        t[ty + 8 * j][tx] = w[(size_t)(k0 + ty + 8 * j) * N + n0 + tx];
    __syncthreads();
#pragma unroll
    for (int j = 0; j < 4; j++) {
        float v = t[tx][ty + 8 * j];
        int n = n0 + ty + 8 * j, k = k0 + tx;
        bf16 h = __float2bfloat16(v);
        bf16 l = __float2bfloat16(v - __bfloat162float(h));
        size_t base = (size_t)n * 3 * K;
        *(bf16*)(aug + base + k)         = h;
        *(bf16*)(aug + base + K + k)     = l;
        *(bf16*)(aug + base + 2 * K + k) = h;
    }
}

// ==================== pack_cgT ====================
__global__ void pack_cgT(const float* __restrict__ cg, uint16_t* __restrict__ dst)
{
    __shared__ float t[32][33];
    int bh = blockIdx.z, d0 = blockIdx.x * 32, n0 = blockIdx.y * 32;
    int b = bh >> 3, h = bh & 7;
    int tx = threadIdx.x, ty = threadIdx.y;
#pragma unroll
    for (int j = 0; j < 4; j++) {
        int n = n0 + ty + 8 * j;
        t[ty + 8 * j][tx] = (n < 196) ? cg[((size_t)b*196 + n)*768 + h*96 + d0 + tx] : 0.f;
    }
    __syncthreads();
#pragma unroll
    for (int j = 0; j < 4; j++) {
        int d = d0 + ty + 8 * j, n = n0 + tx;
        float v = t[tx][ty + 8 * j];
        bf16 hv = __float2bfloat16(v);
        bf16 lv = __float2bfloat16(v - __bfloat162float(hv));
        size_t base = ((size_t)bh*96 + d) * 768;
        dst[base + n]       = *(uint16_t*)&hv;
        dst[base + 256 + n] = *(uint16_t*)&lv;
        dst[base + 512 + n] = *(uint16_t*)&hv;
    }
}

// ==================== elementwise kernels ====================
__global__ __launch_bounds__(256) void ln_kernel(
    const float* __restrict__ x, const float* __restrict__ w,
    const float* __restrict__ b, float* __restrict__ y, uint16_t* __restrict__ xA)
{
    int row = blockIdx.x;
    int bb = row / (T_ * N_);
    int t  = (row / N_) % T_;
    int n  = row % N_;
    size_t xrow = ((size_t)(t * B_ + bb) * N_ + n) * 3 * C_;
    const float* xr = x + (size_t)row * C_;
    float v[3], s = 0.f, s2 = 0.f;
#pragma unroll
    for (int i = 0; i < 3; i++) { v[i] = xr[threadIdx.x + i*256]; s += v[i]; s2 += v[i]*v[i]; }
    __shared__ float red[18];
#pragma unroll
    for (int off = 16; off; off >>= 1) {
        s  += __shfl_down_sync(0xffffffffu, s, off);
        s2 += __shfl_down_sync(0xffffffffu, s2, off);
    }
    int wid = threadIdx.x >> 5, lane = threadIdx.x & 31;
    if (lane == 0) { red[wid] = s; red[8+wid] = s2; }
    __syncthreads();
    if (threadIdx.x == 0) {
        float ts = 0.f, ts2 = 0.f;
        for (int i = 0; i < 8; i++) { ts += red[i]; ts2 += red[8+i]; }
        red[16] = ts; red[17] = ts2;
    }
    __syncthreads();
    float mean = red[16] * (1.0f/C_);
    float inv  = rsqrtf(red[17] * (1.0f/C_) - mean*mean + 1e-5f);
    float* yr = y + (size_t)row * C_;
#pragma unroll
    for (int i = 0; i < 3; i++) {
        int c = threadIdx.x + i*256;
        float o = (v[i] - mean) * inv * w[c] + b[c];
        yr[c] = o;
        bf16 h = __float2bfloat16(o);
        xA[xrow + c]         = *(uint16_t*)&h;
        xA[xrow + C_ + c]    = *(uint16_t*)&h;
        bf16 l = __float2bfloat16(o - __bfloat162float(h));
        xA[xrow + 2*C_ + c]  = *(uint16_t*)&l;
    }
}

__global__ void ap_kernel(const float* __restrict__ mem, float* __restrict__ ap)
{
    int idx = blockIdx.x * 256 + threadIdx.x;
    if (idx >= B_*C_) return;
    int z = blockIdx.y;
    int b = idx / C_, c = idx % C_;
    float s = 0.f;
    const float* p = mem + (size_t)b*MEM_*C_ + (size_t)(z * 49)*C_ + c;
#pragma unroll 7
    for (int m = 0; m < 49; m++) s += p[(size_t)m*C_];
    atomicAdd(&ap[idx], s * (1.0f/MEM_));
}

__global__ __launch_bounds__(128) void apw2(
    const float* __restrict__ ap, const float* __restrict__ c_w1,
    const float* __restrict__ c_b1, float* __restrict__ bias2)
{
    int b = blockIdx.y;
    int j = blockIdx.x * 128 + threadIdx.x;
    __shared__ float aps[768];
    for (int k = threadIdx.x; k < 768; k += 128) aps[k] = ap[b * 768 + k];
    __syncthreads();
    const float* wp = c_w1 + (size_t)768 * HID_ + j;
    float a0 = 0.f, a1 = 0.f, a2 = 0.f, a3 = 0.f;
#pragma unroll 8
    for (int k = 0; k < 768; k += 4) {
        a0 = fmaf(aps[k],     wp[(size_t)(k)     * HID_], a0);
        a1 = fmaf(aps[k + 1], wp[(size_t)(k + 1) * HID_], a1);
        a2 = fmaf(aps[k + 2], wp[(size_t)(k + 2) * HID_], a2);
        a3 = fmaf(aps[k + 3], wp[(size_t)(k + 3) * HID_], a3);
    }
    bias2[b * HID_ + j] = c_b1[j] + ((a0 + a1) + (a2 + a3));
}

__global__ __launch_bounds__(256) void final_kernel(
    const float* __restrict__ c2, const float* __restrict__ gateSum,
    const float* __restrict__ memh, const float* __restrict__ w,
    const float* __restrict__ bb, float* __restrict__ y, uint16_t* __restrict__ aug)
{
    int row = blockIdx.x;
    int b = row / MEM_, m = row % MEM_;
    float v[3], s = 0.f, s2 = 0.f;
#pragma unroll
    for (int i = 0; i < 3; i++) {
        int c = threadIdx.x + i*256;
        float g = 1.0f - gateSum[(b*H_ + (c/D_))*MEM_ + m] * (1.0f / N_);
        v[i] = c2[(size_t)row*C_ + c] + g * memh[(size_t)row*C_ + c];
        s += v[i]; s2 += v[i]*v[i];
    }
    __shared__ float red[18];
#pragma unroll
    for (int off = 16; off; off >>= 1) {
        s  += __shfl_down_sync(0xffffffffu, s, off);
        s2 += __shfl_down_sync(0xffffffffu, s2, off);
    }
    int wid = threadIdx.x >> 5, lane = threadIdx.x & 31;
    if (lane == 0) { red[wid] = s; red[8+wid] = s2; }
    __syncthreads();
    if (threadIdx.x == 0) {
        float ts = 0.f, ts2 = 0.f;
        for (int i = 0; i < 8; i++) { ts += red[i]; ts2 += red[8+i]; }
        red[16] = ts; red[17] = ts2;
    }
    __syncthreads();
    float mean = red[16] * (1.0f/C_);
    float inv  = rsqrtf(red[17] * (1.0f/C_) - mean*mean + 1e-5f);
    float* yr = y + (size_t)row * C_;
    size_t base = (size_t)row * 3 * C_;
#pragma unroll
    for (int i = 0; i < 3; i++) {
        int c = threadIdx.x + i*256;
        float o = (v[i] - mean) * inv * w[c] + bb[c];
        yr[c] = o;
        bf16 h = __float2bfloat16(o);
        aug[base + c]        = *(uint16_t*)&h;
        aug[base + C_ + c]   = *(uint16_t*)&h;
        bf16 l = __float2bfloat16(o - __bfloat162float(h));
        aug[base + 2*C_ + c] = *(uint16_t*)&l;
    }
}

__global__ void initmem_kernel(const float* __restrict__ x, float* __restrict__ mem,
                               uint16_t* __restrict__ aug)
{
    int idx = blockIdx.x * 256 + threadIdx.x;
    if (idx >= B_*MEM_*C_/2) return;
    int row = idx / (C_/2), jp = (idx % (C_/2)) * 2;
    int b = row / MEM_, r = row % MEM_;
    float2 v = *(const float2*)(x + (size_t)b*T_*N_*C_ + (size_t)r*C_ + jp);
    *(float2*)(mem + (size_t)row*C_ + jp) = v;
    aug_store(aug, (size_t)row * 3 * C_, C_, jp, v.x, v.y);
}

// ==================== host orchestration ====================
#define SMEM_128 (3 * (128 + 128) * 128)   // 98304
#define SMEM_SM4 (4 * (64 + 128) * 128)    // 98304
#define SMEM_BAT (3 * (128 + 128) * 128)   // 98304

static void gemm_big(const uint16_t* a, const uint16_t* w, const float* bias,
                     float* out, uint16_t* outAug, int M, int N, int K, int mode,
                     cudaStream_t st)
{
    dim3 g(N / 128, (M + 127) / 128);
    gemm_mma<128, 128, 4, 4, 3><<<g, 256, SMEM_128, st>>>(
        (const bf16*)a, (const bf16*)w, bias, out, outAug, M, N, 3 * K, mode);
}
static void gemm_sm(const uint16_t* a, const uint16_t* w, const float* bias,
                    float* out, uint16_t* outAug, int M, int N, int K, int mode,
                    cudaStream_t st)
{
    dim3 g(N / 128, (M + 63) / 64);
    gemm_mma<64, 128, 2, 4, 4><<<g, 256, SMEM_SM4, st>>>(
        (const bf16*)a, (const bf16*)w, bias, out, outAug, M, N, 3 * K, mode);
}

extern "C" void kernel_launch(void* const* d_in, const int* in_sizes, int n_in,
                              void* d_out, int out_size)
{
    const float* cur_fea = (const float*)d_in[0];
    const float* n1w = (const float*)d_in[1];
    const float* n1b = (const float*)d_in[2];
    const float* n2w = (const float*)d_in[3];
    const float* n2b = (const float*)d_in[4];
    const float* c_w1 = (const float*)d_in[5];  const float* c_b1 = (const float*)d_in[6];
    const float* c_w2 = (const float*)d_in[7];  const float* c_b2 = (const float*)d_in[8];
    const float* m_w1 = (const float*)d_in[9];  const float* m_b1 = (const float*)d_in[10];
    const float* m_w2 = (const float*)d_in[11]; const float* m_b2 = (const float*)d_in[12];
    const float* p_w1 = (const float*)d_in[13]; const float* p_b1 = (const float*)d_in[14];
    const float* p_w2 = (const float*)d_in[15]; const float* p_b2 = (const float*)d_in[16];
    const float* q_w = (const float*)d_in[17];  const float* q_b = (const float*)d_in[18];
    const float* k_w = (const float*)d_in[19];  const float* k_b = (const float*)d_in[20];

    cudaFuncSetAttribute((const void*)gemm_mma<128, 128, 4, 4, 3>,
                         cudaFuncAttributeMaxDynamicSharedMemorySize, SMEM_128);
    cudaFuncSetAttribute((const void*)gemm_mma<64, 128, 2, 4, 4>,
                         cudaFuncAttributeMaxDynamicSharedMemorySize, SMEM_SM4);
    cudaFuncSetAttribute((const void*)gemm_bat,
                         cudaFuncAttributeMaxDynamicSharedMemorySize, SMEM_BAT);

    static cudaStream_t sS = nullptr;
    static cudaEvent_t eA, eK, eCG, eS2;
    if (!sS) {
        cudaStreamCreateWithFlags(&sS, cudaStreamNonBlocking);
        cudaEventCreateWithFlags(&eA,  cudaEventDisableTiming);
        cudaEventCreateWithFlags(&eK,  cudaEventDisableTiming);
        cudaEventCreateWithFlags(&eCG, cudaEventDisableTiming);
        cudaEventCreateWithFlags(&eS2, cudaEventDisableTiming);
    }

    float *x, *cg, *memh, *c2, *gate, *ap, *bias2, *memA, *memB;
    cudaGetSymbolAddress((void**)&x, g_x);       cudaGetSymbolAddress((void**)&cg, g_cg);
    cudaGetSymbolAddress((void**)&memh, g_memh);
    cudaGetSymbolAddress((void**)&c2, g_c2);     cudaGetSymbolAddress((void**)&gate, g_gate);
    cudaGetSymbolAddress((void**)&ap, g_ap);     cudaGetSymbolAddress((void**)&bias2, g_bias2);
    cudaGetSymbolAddress((void**)&memA, g_memA); cudaGetSymbolAddress((void**)&memB, g_memB);

    uint16_t *xA, *hidCA, *hidMA, *cgA, *cA, *memAg, *Q3, *K3, *oT3, *cgT3;
    uint16_t *wc1, *wc2, *wm1, *wm2, *wp1, *wp2, *wq, *wk;
    cudaGetSymbolAddress((void**)&xA, g_xA);
    cudaGetSymbolAddress((void**)&hidCA, g_hidCA);
    cudaGetSymbolAddress((void**)&hidMA, g_hidMA);
    cudaGetSymbolAddress((void**)&cgA, g_cgA);   cudaGetSymbolAddress((void**)&cA, g_cA);
    cudaGetSymbolAddress((void**)&memAg, g_memAg);
    cudaGetSymbolAddress((void**)&Q3, g_Q3);     cudaGetSymbolAddress((void**)&K3, g_K3);
    cudaGetSymbolAddress((void**)&oT3, g_oT3);   cudaGetSymbolAddress((void**)&cgT3, g_cgT3);
    cudaGetSymbolAddress((void**)&wc1, g_wc1);   cudaGetSymbolAddress((void**)&wc2, g_wc2);
    cudaGetSymbolAddress((void**)&wm1, g_wm1);   cudaGetSymbolAddress((void**)&wm2, g_wm2);
    cudaGetSymbolAddress((void**)&wp1, g_wp1);   cudaGetSymbolAddress((void**)&wp2, g_wp2);
    cudaGetSymbolAddress((void**)&wq, g_wq);     cudaGetSymbolAddress((void**)&wk, g_wk);

    WS8 ws;
    ws.src[0] = c_w1; ws.dst[0] = wc1; ws.K[0] = C_;   ws.N[0] = HID_;
    ws.src[1] = c_w2; ws.dst[1] = wc2; ws.K[1] = HID_; ws.N[1] = C_;
    ws.src[2] = m_w1; ws.dst[2] = wm1; ws.K[2] = C_;   ws.N[2] = HID_;
    ws.src[3] = m_w2; ws.dst[3] = wm2; ws.K[3] = HID_; ws.N[3] = C_;
    ws.src[4] = p_w1; ws.dst[4] = wp1; ws.K[4] = C_;   ws.N[4] = HID_;
    ws.src[5] = p_w2; ws.dst[5] = wp2; ws.K[5] = HID_; ws.N[5] = C_;
    ws.src[6] = q_w;  ws.dst[6] = wq;  ws.K[6] = C_;   ws.N[6] = C_;
    ws.src[7] = k_w;  ws.dst[7] = wk;  ws.K[7] = C_;   ws.N[7] = C_;
    dim3 wb(32, 8);
    wsplitAll<<<dim3(96, 96, 8), wb>>>(ws);

    ln_kernel<<<B_*T_*N_, 256>>>(cur_fea, n1w, n1b, x, xA);
    initmem_kernel<<<(B_*MEM_*C_/2 + 255)/256, 256>>>(x, memA, memAg);

    float* mcur = memA;
    float* mnxt = memB;

    for (int t = 1; t < T_; t++) {
        cudaEventRecord(eA, 0);
        cudaStreamWaitEvent(sS, eA, 0);

        // ---- stream S: m-chain (k first to release eK early) ----
        gemm_sm (memAg, wk, k_b, nullptr, K3, ROWS_, C_, C_, 32, sS);          // k -> K3
        cudaEventRecord(eK, sS);
        gemm_big(memAg, wm1, m_b1, nullptr, hidMA, ROWS_, HID_, C_, 1|4, sS);  // fc1_m
        gemm_sm (hidMA, wm2, m_b2, memh, nullptr, ROWS_, C_, HID_, 2, sS);     // fc2_m

        // ---- legacy stream L: c-chain ----
        cudaMemsetAsync(ap, 0, B_*C_*sizeof(float), 0);
        ap_kernel<<<dim3((B_*C_ + 255)/256, 4), 256>>>(mcur, ap);
        apw2<<<dim3(HID_/128, B_), 128>>>(ap, c_w1, c_b1, bias2);
        const uint16_t* feaA = xA + (size_t)t * ROWS_ * 3 * C_;
        gemm_big(feaA, wc1, bias2, nullptr, hidCA, ROWS_, HID_, C_, 1|4|8, 0); // fc1_c
        gemm_sm (hidCA, wc2, c_b2, cg, cgA, ROWS_, C_, HID_, 2|4, 0);          // fc2_c
        cudaEventRecord(eCG, 0);
        cudaStreamWaitEvent(sS, eCG, 0);
        pack_cgT<<<dim3(3, 8, 64), wb, 0, sS>>>(cg, cgT3);                     // on S
        cudaEventRecord(eS2, sS);

        gemm_sm (cgA, wq, q_b, nullptr, Q3, ROWS_, C_, C_, 16, 0);             // q -> Q3
        cudaMemsetAsync(gate, 0, B_*H_*MEM_*sizeof(float), 0);
        cudaStreamWaitEvent(0, eK, 0);
        gemm_bat<<<dim3(2, 2, 64), 256, SMEM_BAT>>>(
            (const bf16*)Q3, (const bf16*)K3, oT3, gate, nullptr, 196, 196, 384, 0);
        cudaStreamWaitEvent(0, eS2, 0);
        gemm_bat<<<dim3(1, 2, 64), 256, SMEM_BAT>>>(
            (const bf16*)oT3, (const bf16*)cgT3, nullptr, nullptr, cA, 196, 96, 768, 1);

        gemm_big(cA, wp1, p_b1, nullptr, hidCA, ROWS_, HID_, C_, 1|4, 0);      // fc1_p
        gemm_sm (hidCA, wp2, p_b2, c2, nullptr, ROWS_, C_, HID_, 2, 0);        // fc2_p

        float* dst = (t == T_ - 1) ? (float*)d_out : mnxt;
        final_kernel<<<B_*MEM_, 256>>>(c2, gate, memh, n2w, n2b, dst, memAg);

        float* tmp = mcur; mcur = mnxt; mnxt = tmp;
    }
}

// round 17
// speedup vs baseline: 1.0757x; 1.0518x over previous
#include <cuda_runtime.h>
#include <cuda_bf16.h>
#include <math.h>
#include <stdint.h>

#define B_   8
#define T_   16
#define N_   196
#define C_   768
#define H_   8
#define D_   96
#define MEM_ 196
#define HID_ 3072
#define ROWS_ 1568
#define SCALE_ 0.1020620726159657f

typedef __nv_bfloat16 bf16;

// ---------------- fp32 scratch ----------------
__device__ __align__(256) float g_x   [B_*T_*N_*C_];
__device__ __align__(256) float g_cg  [ROWS_*C_];
__device__ __align__(256) float g_memh[ROWS_*C_];
__device__ __align__(256) float g_c2  [ROWS_*C_];
__device__ __align__(256) float g_gate[B_*H_*MEM_];
__device__ __align__(256) float g_ap  [B_*C_];
__device__ __align__(256) float g_bias2[B_*HID_];
__device__ __align__(256) float g_memA[ROWS_*C_];
__device__ __align__(256) float g_memB[ROWS_*C_];

// ---------------- augmented bf16 activations ----------------
__device__ __align__(256) uint16_t g_xA  [T_*B_*N_*3*C_];
__device__ __align__(256) uint16_t g_hidCA[ROWS_*3*HID_];
__device__ __align__(256) uint16_t g_hidMA[ROWS_*3*HID_];
__device__ __align__(256) uint16_t g_cgA [ROWS_*3*C_];
__device__ __align__(256) uint16_t g_cA  [ROWS_*3*C_];
__device__ __align__(256) uint16_t g_memAg[ROWS_*3*C_];

// attention aug operands (zero-init; pads never written)
__device__ __align__(256) uint16_t g_Q3 [64*196*384];
__device__ __align__(256) uint16_t g_K3 [64*196*384];
__device__ __align__(256) uint16_t g_oT3[64*196*768];
__device__ __align__(256) uint16_t g_cgT3[64*96*768];

// weights augmented [N][3K] = [hi|lo|hi]
__device__ __align__(256) uint16_t g_wc1[HID_*3*C_];
__device__ __align__(256) uint16_t g_wc2[C_*3*HID_];
__device__ __align__(256) uint16_t g_wm1[HID_*3*C_];
__device__ __align__(256) uint16_t g_wm2[C_*3*HID_];
__device__ __align__(256) uint16_t g_wp1[HID_*3*C_];
__device__ __align__(256) uint16_t g_wp2[C_*3*HID_];
__device__ __align__(256) uint16_t g_wq [C_*3*C_];
__device__ __align__(256) uint16_t g_wk [C_*3*C_];

__device__ __forceinline__ float gelu_exact(float x) {
    return 0.5f * x * (1.0f + erff(x * 0.70710678118654752f));
}
__device__ __forceinline__ uint32_t smem_u32(const void* p) {
    uint32_t a;
    asm("{ .reg .u64 t; cvta.to.shared.u64 t, %1; cvt.u32.u64 %0, t; }" : "=r"(a) : "l"(p));
    return a;
}
__device__ __forceinline__ void cp16(uint32_t dst, const void* src, int pred) {
    int sz = pred ? 16 : 0;
    asm volatile("cp.async.cg.shared.global [%0], [%1], 16, %2;" :: "r"(dst), "l"(src), "r"(sz) : "memory");
}
__device__ __forceinline__ uint32_t swz(uint32_t o) { return o ^ ((o >> 3) & 0x70); }

#define LDSM4(r0, r1, r2, r3, addr) \
    asm volatile("ldmatrix.sync.aligned.m8n8.x4.shared.b16 {%0,%1,%2,%3}, [%4];" \
        : "=r"(r0), "=r"(r1), "=r"(r2), "=r"(r3) : "r"(addr))

#define MMA16816(d, a, b0, b1) \
    asm volatile("mma.sync.aligned.m16n8k16.row.col.f32.bf16.bf16.f32 " \
        "{%0,%1,%2,%3}, {%4,%5,%6,%7}, {%8,%9}, {%0,%1,%2,%3};" \
        : "+f"((d)[0]), "+f"((d)[1]), "+f"((d)[2]), "+f"((d)[3]) \
        : "r"((a)[0]), "r"((a)[1]), "r"((a)[2]), "r"((a)[3]), "r"(b0), "r"(b1))

__device__ __forceinline__ void aug_store(uint16_t* aug, size_t base, int Ncols, int col,
                                          float v0, float v1)
{
    bf16 h0 = __float2bfloat16(v0), h1 = __float2bfloat16(v1);
    __nv_bfloat162 hh = __halves2bfloat162(h0, h1);
    __nv_bfloat162 ll = __halves2bfloat162(__float2bfloat16(v0 - __bfloat162float(h0)),
                                           __float2bfloat16(v1 - __bfloat162float(h1)));
    *(uint32_t*)(aug + base + col)             = *(uint32_t*)&hh;
    *(uint32_t*)(aug + base + Ncols + col)     = *(uint32_t*)&hh;
    *(uint32_t*)(aug + base + 2 * Ncols + col) = *(uint32_t*)&ll;
}

// ==================== GEMM: single 64x128 tile for all weight GEMMs ====================
// mode bits: 1=gelu, 2=fp32 out, 4=aug out, 8=per-batch bias, 16=Q3 aug, 32=K3 aug
#define GS 3

template<int BM, int BN, int MT, int NT>
__global__ __launch_bounds__(256, 2) void gemm_mma(
    const bf16* __restrict__ A, const bf16* __restrict__ Bw,
    const float* __restrict__ bias, float* __restrict__ out,
    uint16_t* __restrict__ outAug, int M, int N, int K3, int mode)
{
    constexpr int A_BYTES = BM * 128;
    constexpr int STG = (BM + BN) * 128;
    extern __shared__ __align__(1024) char smem[];
    uint32_t sb = smem_u32(smem);
    int tid = threadIdx.x, wid = tid >> 5, lane = tid & 31;
    int bm = blockIdx.y * BM, bn = blockIdx.x * BN;
    int m0w = (wid & 1) * (MT * 16);
    int n0w = (wid >> 1) * (NT * 8);
    int NC = K3 >> 6;

    auto load_stage = [&](int c) {
        uint32_t stage = sb + (c % GS) * STG;
        int k0 = c << 6;
        constexpr int TOT = (BM + BN) * 8;
#pragma unroll
        for (int g0 = 0; g0 < TOT; g0 += 256) {
            int g = g0 + tid;
            int isB = (g >= BM * 8);
            int q = isB ? (g - BM * 8) : g;
            int row = q >> 3, c16 = q & 7;
            uint32_t dst = stage + (isB ? A_BYTES : 0) + swz((row << 7) + (c16 << 4));
            const bf16* src;
            int pred = 1;
            if (!isB) {
                int gr = bm + row; pred = gr < M;
                src = A + (size_t)(pred ? gr : 0) * K3 + k0 + (c16 << 3);
            } else {
                int gr = bn + row;
                src = Bw + (size_t)gr * K3 + k0 + (c16 << 3);
            }
            cp16(dst, src, pred);
        }
        asm volatile("cp.async.commit_group;" ::: "memory");
    };

    float acc[MT][NT][4];
#pragma unroll
    for (int mt = 0; mt < MT; mt++)
#pragma unroll
        for (int nt = 0; nt < NT; nt++)
#pragma unroll
            for (int i = 0; i < 4; i++) acc[mt][nt][i] = 0.f;

    load_stage(0);
    load_stage(1);

    for (int c = 0; c < NC; c++) {
        if (c == NC - 1) asm volatile("cp.async.wait_group 0;" ::: "memory");
        else             asm volatile("cp.async.wait_group 1;" ::: "memory");
        __syncthreads();
        if (c + 2 < NC) load_stage(c + 2);

        uint32_t sA = sb + (c % GS) * STG;
        uint32_t sB = sA + A_BYTES;
#pragma unroll
        for (int ks = 0; ks < 4; ks++) {
            uint32_t a[MT][4], bfr[NT / 2][4];
#pragma unroll
            for (int mt = 0; mt < MT; mt++) {
                int row = m0w + mt * 16 + (lane & 15);
                int ch = ks * 2 + (lane >> 4);
                uint32_t ad = sA + swz((uint32_t)(row << 7) + (ch << 4));
                LDSM4(a[mt][0], a[mt][1], a[mt][2], a[mt][3], ad);
            }
#pragma unroll
            for (int bp = 0; bp < NT / 2; bp++) {
                int row = n0w + bp * 16 + (lane & 7) + ((lane & 16) >> 1);
                int ch = ks * 2 + ((lane & 8) >> 3);
                uint32_t ad = sB + swz((uint32_t)(row << 7) + (ch << 4));
                LDSM4(bfr[bp][0], bfr[bp][1], bfr[bp][2], bfr[bp][3], ad);
            }
#pragma unroll
            for (int mt = 0; mt < MT; mt++)
#pragma unroll
                for (int nt = 0; nt < NT; nt++)
                    MMA16816(acc[mt][nt], a[mt],
                             bfr[nt >> 1][(nt & 1) * 2], bfr[nt >> 1][(nt & 1) * 2 + 1]);
        }
    }

    if (mode & 48) {
        int isK = (mode & 32) != 0;
#pragma unroll
        for (int mt = 0; mt < MT; mt++) {
#pragma unroll
            for (int half = 0; half < 2; half++) {
                int r = bm + m0w + mt * 16 + (lane >> 2) + half * 8;
                if (r >= M) continue;
                int b = r / 196, n = r % 196;
#pragma unroll
                for (int nt = 0; nt < NT; nt++) {
                    int col = bn + n0w + nt * 8 + ((lane & 3) << 1);
                    int h = col / 96, d = col - h * 96;
                    float v0 = acc[mt][nt][half * 2]     + bias[col];
                    float v1 = acc[mt][nt][half * 2 + 1] + bias[col + 1];
                    bf16 h0 = __float2bfloat16(v0), h1 = __float2bfloat16(v1);
                    __nv_bfloat162 hh = __halves2bfloat162(h0, h1);
                    __nv_bfloat162 ll = __halves2bfloat162(
                        __float2bfloat16(v0 - __bfloat162float(h0)),
                        __float2bfloat16(v1 - __bfloat162float(h1)));
                    uint32_t* qp = (uint32_t*)(outAug +
                        ((size_t)((b << 3) + h) * 196 + n) * 384);
                    int di = d >> 1;
                    qp[di] = *(uint32_t*)&hh;
                    if (isK) { qp[64 + di] = *(uint32_t*)&ll; qp[128 + di] = *(uint32_t*)&hh; }
                    else     { qp[64 + di] = *(uint32_t*)&hh; qp[128 + di] = *(uint32_t*)&ll; }
                }
            }
        }
        return;
    }

#pragma unroll
    for (int mt = 0; mt < MT; mt++) {
        int r0 = bm + m0w + mt * 16 + (lane >> 2);
        int r1 = r0 + 8;
#pragma unroll
        for (int nt = 0; nt < NT; nt++) {
            int col = bn + n0w + nt * 8 + ((lane & 3) << 1);
            if (r0 < M) {
                int bb = (mode & 8) ? (r0 / 196) * N : 0;
                float v0 = acc[mt][nt][0] + bias[bb + col];
                float v1 = acc[mt][nt][1] + bias[bb + col + 1];
                if (mode & 1) { v0 = gelu_exact(v0); v1 = gelu_exact(v1); }
                if (mode & 2) *(float2*)(out + (size_t)r0 * N + col) = make_float2(v0, v1);
                if (mode & 4) aug_store(outAug, (size_t)r0 * 3 * N, N, col, v0, v1);
            }
            if (r1 < M) {
                int bb = (mode & 8) ? (r1 / 196) * N : 0;
                float v2 = acc[mt][nt][2] + bias[bb + col];
                float v3 = acc[mt][nt][3] + bias[bb + col + 1];
                if (mode & 1) { v2 = gelu_exact(v2); v3 = gelu_exact(v3); }
                if (mode & 2) *(float2*)(out + (size_t)r1 * N + col) = make_float2(v2, v3);
                if (mode & 4) aug_store(outAug, (size_t)r1 * 3 * N, N, col, v2, v3);
            }
        }
    }
}

// ==================== batched aug GEMM for attention (R13 proven) ====================
__global__ __launch_bounds__(256, 2) void gemm_bat(
    const bf16* __restrict__ Aall, const bf16* __restrict__ Ball,
    uint16_t* __restrict__ oT3, float* __restrict__ gateSum,
    uint16_t* __restrict__ cAug, int MA, int NB, int K3, int epi)
{
    constexpr int BM = 128, BN = 128, MT = 4, NT = 4;
    constexpr int A_BYTES = BM * 128;
    constexpr int STG = (BM + BN) * 128;
    extern __shared__ __align__(1024) char smem[];
    uint32_t sb = smem_u32(smem);
    int tid = threadIdx.x, wid = tid >> 5, lane = tid & 31;
    int bz = blockIdx.z;
    const bf16* A = Aall + (size_t)bz * MA * K3;
    const bf16* Bw = Ball + (size_t)bz * NB * K3;
    int bm = blockIdx.y * BM, bn = blockIdx.x * BN;
    int m0w = (wid & 1) * 64;
    int n0w = (wid >> 1) * 32;
    int NC = K3 >> 6;

    auto load_stage = [&](int c) {
        uint32_t stage = sb + (c % GS) * STG;
        int k0 = c << 6;
#pragma unroll
        for (int g0 = 0; g0 < (BM + BN) * 8; g0 += 256) {
            int g = g0 + tid;
            int isB = (g >= BM * 8);
            int q = isB ? (g - BM * 8) : g;
            int row = q >> 3, c16 = q & 7;
            uint32_t dst = stage + (isB ? A_BYTES : 0) + swz((row << 7) + (c16 << 4));
            const bf16* src;
            int pred;
            if (!isB) {
                int gr = bm + row; pred = gr < MA;
                src = A + (size_t)(pred ? gr : 0) * K3 + k0 + (c16 << 3);
            } else {
                int gr = bn + row; pred = gr < NB;
                src = Bw + (size_t)(pred ? gr : 0) * K3 + k0 + (c16 << 3);
            }
            cp16(dst, src, pred);
        }
        asm volatile("cp.async.commit_group;" ::: "memory");
    };

    float acc[MT][NT][4];
#pragma unroll
    for (int mt = 0; mt < MT; mt++)
#pragma unroll
        for (int nt = 0; nt < NT; nt++)
#pragma unroll
            for (int i = 0; i < 4; i++) acc[mt][nt][i] = 0.f;

    load_stage(0);
    load_stage(1);

    for (int c = 0; c < NC; c++) {
        if (c == NC - 1) asm volatile("cp.async.wait_group 0;" ::: "memory");
        else             asm volatile("cp.async.wait_group 1;" ::: "memory");
        __syncthreads();
        if (c + 2 < NC) load_stage(c + 2);

        uint32_t sA = sb + (c % GS) * STG;
        uint32_t sB = sA + A_BYTES;
#pragma unroll
        for (int ks = 0; ks < 4; ks++) {
            uint32_t a[MT][4], bfr[NT / 2][4];
#pragma unroll
            for (int mt = 0; mt < MT; mt++) {
                int row = m0w + mt * 16 + (lane & 15);
                int ch = ks * 2 + (lane >> 4);
                uint32_t ad = sA + swz((uint32_t)(row << 7) + (ch << 4));
                LDSM4(a[mt][0], a[mt][1], a[mt][2], a[mt][3], ad);
            }
#pragma unroll
            for (int bp = 0; bp < NT / 2; bp++) {
                int row = n0w + bp * 16 + (lane & 7) + ((lane & 16) >> 1);
                int ch = ks * 2 + ((lane & 8) >> 3);
                uint32_t ad = sB + swz((uint32_t)(row << 7) + (ch << 4));
                LDSM4(bfr[bp][0], bfr[bp][1], bfr[bp][2], bfr[bp][3], ad);
            }
#pragma unroll
            for (int mt = 0; mt < MT; mt++)
#pragma unroll
                for (int nt = 0; nt < NT; nt++)
                    MMA16816(acc[mt][nt], a[mt],
                             bfr[nt >> 1][(nt & 1) * 2], bfr[nt >> 1][(nt & 1) * 2 + 1]);
        }
    }

    int bb = bz >> 3, hh = bz & 7;
    if (epi == 0) {
#pragma unroll
        for (int nt = 0; nt < NT; nt++) {
            int col = bn + n0w + nt * 8 + ((lane & 3) << 1);
            float g0 = 0.f, g1 = 0.f;
#pragma unroll
            for (int mt = 0; mt < MT; mt++) {
                int r0 = bm + m0w + mt * 16 + (lane >> 2);
                int r1 = r0 + 8;
                float v[4];
                v[0] = 1.f / (1.f + expf(-acc[mt][nt][0] * SCALE_));
                v[1] = 1.f / (1.f + expf(-acc[mt][nt][1] * SCALE_));
                v[2] = 1.f / (1.f + expf(-acc[mt][nt][2] * SCALE_));
                v[3] = 1.f / (1.f + expf(-acc[mt][nt][3] * SCALE_));
#pragma unroll
                for (int i = 0; i < 4; i++) {
                    int n = (i < 2) ? r0 : r1;
                    int m = col + (i & 1);
                    if (n < 196 && m < 196) {
                        float vv = v[i];
                        bf16 h = __float2bfloat16(vv);
                        bf16 l = __float2bfloat16(vv - __bfloat162float(h));
                        size_t base = ((size_t)bz * 196 + m) * 768;
                        oT3[base + n]       = *(uint16_t*)&h;
                        oT3[base + 256 + n] = *(uint16_t*)&h;
                        oT3[base + 512 + n] = *(uint16_t*)&l;
                        if (i & 1) g1 += vv; else g0 += vv;
                    }
                }
            }
            if (col < 196)     atomicAdd(gateSum + (size_t)bz * 196 + col, g0);
            if (col + 1 < 196) atomicAdd(gateSum + (size_t)bz * 196 + col + 1, g1);
        }
    } else {
#pragma unroll
        for (int mt = 0; mt < MT; mt++) {
            int r0 = bm + m0w + mt * 16 + (lane >> 2);
            int r1 = r0 + 8;
#pragma unroll
            for (int nt = 0; nt < NT; nt++) {
                int col = bn + n0w + nt * 8 + ((lane & 3) << 1);
                if (col + 1 < 96) {
                    if (r0 < 196)
                        aug_store(cAug, (size_t)(bb*196 + r0) * 3 * C_, C_, hh*96 + col,
                                  acc[mt][nt][0], acc[mt][nt][1]);
                    if (r1 < 196)
                        aug_store(cAug, (size_t)(bb*196 + r1) * 3 * C_, C_, hh*96 + col,
                                  acc[mt][nt][2], acc[mt][nt][3]);
                }
            }
        }
    }
}

// ==================== combined weight split ====================
struct WS8 {
    const float* src[8];
    uint16_t* dst[8];
    int K[8];
    int N[8];
};

__global__ void wsplitAll(WS8 p)
{
    int id = blockIdx.z;
    int K = p.K[id], N = p.N[id];
    int n0 = blockIdx.x * 32, k0 = blockIdx.y * 32;
    if (n0 >= N || k0 >= K) return;
    const float* w = p.src[id];
    uint16_t* aug = p.dst[id];
    __shared__ float t[32][33];
    int tx = threadIdx.x, ty = threadIdx.y;
#pragma unroll
    for (int j = 0; j < 4; j++)
        t[ty + 8 * j][tx] = w[(size_t)(k0 + ty + 8 * j) * N + n0 + tx];
    __syncthreads();
#pragma unroll
    for (int j = 0; j < 4; j++) {
        float v = t[tx][ty + 8 * j];
        int n = n0 + ty + 8 * j, k = k0 + tx;
        bf16 h = __float2bfloat16(v);
        bf16 l = __float2bfloat16(v - __bfloat162float(h));
        size_t base = (size_t)n * 3 * K;
        *(bf16*)(aug + base + k)         = h;
        *(bf16*)(aug + base + K + k)     = l;
        *(bf16*)(aug + base + 2 * K + k) = h;
    }
}

// ==================== pack_cgT ====================
__global__ void pack_cgT(const float* __restrict__ cg, uint16_t* __restrict__ dst)
{
    __shared__ float t[32][33];
    int bh = blockIdx.z, d0 = blockIdx.x * 32, n0 = blockIdx.y * 32;
    int b = bh >> 3, h = bh & 7;
    int tx = threadIdx.x, ty = threadIdx.y;
#pragma unroll
    for (int j = 0; j < 4; j++) {
        int n = n0 + ty + 8 * j;
        t[ty + 8 * j][tx] = (n < 196) ? cg[((size_t)b*196 + n)*768 + h*96 + d0 + tx] : 0.f;
    }
    __syncthreads();
#pragma unroll
    for (int j = 0; j < 4; j++) {
        int d = d0 + ty + 8 * j, n = n0 + tx;
        float v = t[tx][ty + 8 * j];
        bf16 hv = __float2bfloat16(v);
        bf16 lv = __float2bfloat16(v - __bfloat162float(hv));
        size_t base = ((size_t)bh*96 + d) * 768;
        dst[base + n]       = *(uint16_t*)&hv;
        dst[base + 256 + n] = *(uint16_t*)&lv;
        dst[base + 512 + n] = *(uint16_t*)&hv;
    }
}

// ==================== elementwise kernels ====================
__global__ __launch_bounds__(256) void ln_kernel(
    const float* __restrict__ x, const float* __restrict__ w,
    const float* __restrict__ b, float* __restrict__ y, uint16_t* __restrict__ xA)
{
    int row = blockIdx.x;
    int bb = row / (T_ * N_);
    int t  = (row / N_) % T_;
    int n  = row % N_;
    size_t xrow = ((size_t)(t * B_ + bb) * N_ + n) * 3 * C_;
    const float* xr = x + (size_t)row * C_;
    float v[3], s = 0.f, s2 = 0.f;
#pragma unroll
    for (int i = 0; i < 3; i++) { v[i] = xr[threadIdx.x + i*256]; s += v[i]; s2 += v[i]*v[i]; }
    __shared__ float red[18];
#pragma unroll
    for (int off = 16; off; off >>= 1) {
        s  += __shfl_down_sync(0xffffffffu, s, off);
        s2 += __shfl_down_sync(0xffffffffu, s2, off);
    }
    int wid = threadIdx.x >> 5, lane = threadIdx.x & 31;
    if (lane == 0) { red[wid] = s; red[8+wid] = s2; }
    __syncthreads();
    if (threadIdx.x == 0) {
        float ts = 0.f, ts2 = 0.f;
        for (int i = 0; i < 8; i++) { ts += red[i]; ts2 += red[8+i]; }
        red[16] = ts; red[17] = ts2;
    }
    __syncthreads();
    float mean = red[16] * (1.0f/C_);
    float inv  = rsqrtf(red[17] * (1.0f/C_) - mean*mean + 1e-5f);
    float* yr = y + (size_t)row * C_;
#pragma unroll
    for (int i = 0; i < 3; i++) {
        int c = threadIdx.x + i*256;
        float o = (v[i] - mean) * inv * w[c] + b[c];
        yr[c] = o;
        bf16 h = __float2bfloat16(o);
        xA[xrow + c]         = *(uint16_t*)&h;
        xA[xrow + C_ + c]    = *(uint16_t*)&h;
        bf16 l = __float2bfloat16(o - __bfloat162float(h));
        xA[xrow + 2*C_ + c]  = *(uint16_t*)&l;
    }
}

__global__ void ap_kernel(const float* __restrict__ mem, float* __restrict__ ap)
{
    int idx = blockIdx.x * 256 + threadIdx.x;
    if (idx >= B_*C_) return;
    int z = blockIdx.y;
    int b = idx / C_, c = idx % C_;
    float s = 0.f;
    const float* p = mem + (size_t)b*MEM_*C_ + (size_t)(z * 49)*C_ + c;
#pragma unroll 7
    for (int m = 0; m < 49; m++) s += p[(size_t)m*C_];
    atomicAdd(&ap[idx], s * (1.0f/MEM_));
}

__global__ __launch_bounds__(128) void apw2(
    const float* __restrict__ ap, const float* __restrict__ c_w1,
    const float* __restrict__ c_b1, float* __restrict__ bias2)
{
    int b = blockIdx.y;
    int j = blockIdx.x * 128 + threadIdx.x;
    __shared__ float aps[768];
    for (int k = threadIdx.x; k < 768; k += 128) aps[k] = ap[b * 768 + k];
    __syncthreads();
    const float* wp = c_w1 + (size_t)768 * HID_ + j;
    float a0 = 0.f, a1 = 0.f, a2 = 0.f, a3 = 0.f;
#pragma unroll 8
    for (int k = 0; k < 768; k += 4) {
        a0 = fmaf(aps[k],     wp[(size_t)(k)     * HID_], a0);
        a1 = fmaf(aps[k + 1], wp[(size_t)(k + 1) * HID_], a1);
        a2 = fmaf(aps[k + 2], wp[(size_t)(k + 2) * HID_], a2);
        a3 = fmaf(aps[k + 3], wp[(size_t)(k + 3) * HID_], a3);
    }
    bias2[b * HID_ + j] = c_b1[j] + ((a0 + a1) + (a2 + a3));
}

__global__ __launch_bounds__(256) void final_kernel(
    const float* __restrict__ c2, const float* __restrict__ gateSum,
    const float* __restrict__ memh, const float* __restrict__ w,
    const float* __restrict__ bb, float* __restrict__ y, uint16_t* __restrict__ aug)
{
    int row = blockIdx.x;
    int b = row / MEM_, m = row % MEM_;
    float v[3], s = 0.f, s2 = 0.f;
#pragma unroll
    for (int i = 0; i < 3; i++) {
        int c = threadIdx.x + i*256;
        float g = 1.0f - gateSum[(b*H_ + (c/D_))*MEM_ + m] * (1.0f / N_);
        v[i] = c2[(size_t)row*C_ + c] + g * memh[(size_t)row*C_ + c];
        s += v[i]; s2 += v[i]*v[i];
    }
    __shared__ float red[18];
#pragma unroll
    for (int off = 16; off; off >>= 1) {
        s  += __shfl_down_sync(0xffffffffu, s, off);
        s2 += __shfl_down_sync(0xffffffffu, s2, off);
    }
    int wid = threadIdx.x >> 5, lane = threadIdx.x & 31;
    if (lane == 0) { red[wid] = s; red[8+wid] = s2; }
    __syncthreads();
    if (threadIdx.x == 0) {
        float ts = 0.f, ts2 = 0.f;
        for (int i = 0; i < 8; i++) { ts += red[i]; ts2 += red[8+i]; }
        red[16] = ts; red[17] = ts2;
    }
    __syncthreads();
    float mean = red[16] * (1.0f/C_);
    float inv  = rsqrtf(red[17] * (1.0f/C_) - mean*mean + 1e-5f);
    float* yr = y + (size_t)row * C_;
    size_t base = (size_t)row * 3 * C_;
#pragma unroll
    for (int i = 0; i < 3; i++) {
        int c = threadIdx.x + i*256;
        float o = (v[i] - mean) * inv * w[c] + bb[c];
        yr[c] = o;
        bf16 h = __float2bfloat16(o);
        aug[base + c]        = *(uint16_t*)&h;
        aug[base + C_ + c]   = *(uint16_t*)&h;
        bf16 l = __float2bfloat16(o - __bfloat162float(h));
        aug[base + 2*C_ + c] = *(uint16_t*)&l;
    }
}

__global__ void initmem_kernel(const float* __restrict__ x, float* __restrict__ mem,
                               uint16_t* __restrict__ aug)
{
    int idx = blockIdx.x * 256 + threadIdx.x;
    if (idx >= B_*MEM_*C_/2) return;
    int row = idx / (C_/2), jp = (idx % (C_/2)) * 2;
    int b = row / MEM_, r = row % MEM_;
    float2 v = *(const float2*)(x + (size_t)b*T_*N_*C_ + (size_t)r*C_ + jp);
    *(float2*)(mem + (size_t)row*C_ + jp) = v;
    aug_store(aug, (size_t)row * 3 * C_, C_, jp, v.x, v.y);
}

// ==================== host orchestration ====================
#define SMEM_SM  (GS * (64 + 128) * 128)    // 73728
#define SMEM_BAT (GS * (128 + 128) * 128)   // 98304

// single 64x128 tile GEMM for all weight GEMMs
static void gemm64(const uint16_t* a, const uint16_t* w, const float* bias,
                   float* out, uint16_t* outAug, int M, int N, int K, int mode,
                   cudaStream_t st)
{
    dim3 g(N / 128, (M + 63) / 64);
    gemm_mma<64, 128, 2, 4><<<g, 256, SMEM_SM, st>>>(
        (const bf16*)a, (const bf16*)w, bias, out, outAug, M, N, 3 * K, mode);
}

extern "C" void kernel_launch(void* const* d_in, const int* in_sizes, int n_in,
                              void* d_out, int out_size)
{
    const float* cur_fea = (const float*)d_in[0];
    const float* n1w = (const float*)d_in[1];
    const float* n1b = (const float*)d_in[2];
    const float* n2w = (const float*)d_in[3];
    const float* n2b = (const float*)d_in[4];
    const float* c_w1 = (const float*)d_in[5];  const float* c_b1 = (const float*)d_in[6];
    const float* c_w2 = (const float*)d_in[7];  const float* c_b2 = (const float*)d_in[8];
    const float* m_w1 = (const float*)d_in[9];  const float* m_b1 = (const float*)d_in[10];
    const float* m_w2 = (const float*)d_in[11]; const float* m_b2 = (const float*)d_in[12];
    const float* p_w1 = (const float*)d_in[13]; const float* p_b1 = (const float*)d_in[14];
    const float* p_w2 = (const float*)d_in[15]; const float* p_b2 = (const float*)d_in[16];
    const float* q_w = (const float*)d_in[17];  const float* q_b = (const float*)d_in[18];
    const float* k_w = (const float*)d_in[19];  const float* k_b = (const float*)d_in[20];

    cudaFuncSetAttribute((const void*)gemm_mma<64, 128, 2, 4>,
                         cudaFuncAttributeMaxDynamicSharedMemorySize, SMEM_SM);
    cudaFuncSetAttribute((const void*)gemm_bat,
                         cudaFuncAttributeMaxDynamicSharedMemorySize, SMEM_BAT);

    static cudaStream_t sS = nullptr;
    static cudaEvent_t eA, eK, eCG, eS2;
    if (!sS) {
        cudaStreamCreateWithFlags(&sS, cudaStreamNonBlocking);
        cudaEventCreateWithFlags(&eA,  cudaEventDisableTiming);
        cudaEventCreateWithFlags(&eK,  cudaEventDisableTiming);
        cudaEventCreateWithFlags(&eCG, cudaEventDisableTiming);
        cudaEventCreateWithFlags(&eS2, cudaEventDisableTiming);
    }

    float *x, *cg, *memh, *c2, *gate, *ap, *bias2, *memA, *memB;
    cudaGetSymbolAddress((void**)&x, g_x);       cudaGetSymbolAddress((void**)&cg, g_cg);
    cudaGetSymbolAddress((void**)&memh, g_memh);
    cudaGetSymbolAddress((void**)&c2, g_c2);     cudaGetSymbolAddress((void**)&gate, g_gate);
    cudaGetSymbolAddress((void**)&ap, g_ap);     cudaGetSymbolAddress((void**)&bias2, g_bias2);
    cudaGetSymbolAddress((void**)&memA, g_memA); cudaGetSymbolAddress((void**)&memB, g_memB);

    uint16_t *xA, *hidCA, *hidMA, *cgA, *cA, *memAg, *Q3, *K3, *oT3, *cgT3;
    uint16_t *wc1, *wc2, *wm1, *wm2, *wp1, *wp2, *wq, *wk;
    cudaGetSymbolAddress((void**)&xA, g_xA);
    cudaGetSymbolAddress((void**)&hidCA, g_hidCA);
    cudaGetSymbolAddress((void**)&hidMA, g_hidMA);
    cudaGetSymbolAddress((void**)&cgA, g_cgA);   cudaGetSymbolAddress((void**)&cA, g_cA);
    cudaGetSymbolAddress((void**)&memAg, g_memAg);
    cudaGetSymbolAddress((void**)&Q3, g_Q3);     cudaGetSymbolAddress((void**)&K3, g_K3);
    cudaGetSymbolAddress((void**)&oT3, g_oT3);   cudaGetSymbolAddress((void**)&cgT3, g_cgT3);
    cudaGetSymbolAddress((void**)&wc1, g_wc1);   cudaGetSymbolAddress((void**)&wc2, g_wc2);
    cudaGetSymbolAddress((void**)&wm1, g_wm1);   cudaGetSymbolAddress((void**)&wm2, g_wm2);
    cudaGetSymbolAddress((void**)&wp1, g_wp1);   cudaGetSymbolAddress((void**)&wp2, g_wp2);
    cudaGetSymbolAddress((void**)&wq, g_wq);     cudaGetSymbolAddress((void**)&wk, g_wk);

    WS8 ws;
    ws.src[0] = c_w1; ws.dst[0] = wc1; ws.K[0] = C_;   ws.N[0] = HID_;
    ws.src[1] = c_w2; ws.dst[1] = wc2; ws.K[1] = HID_; ws.N[1] = C_;
    ws.src[2] = m_w1; ws.dst[2] = wm1; ws.K[2] = C_;   ws.N[2] = HID_;
    ws.src[3] = m_w2; ws.dst[3] = wm2; ws.K[3] = HID_; ws.N[3] = C_;
    ws.src[4] = p_w1; ws.dst[4] = wp1; ws.K[4] = C_;   ws.N[4] = HID_;
    ws.src[5] = p_w2; ws.dst[5] = wp2; ws.K[5] = HID_; ws.N[5] = C_;
    ws.src[6] = q_w;  ws.dst[6] = wq;  ws.K[6] = C_;   ws.N[6] = C_;
    ws.src[7] = k_w;  ws.dst[7] = wk;  ws.K[7] = C_;   ws.N[7] = C_;
    dim3 wb(32, 8);
    wsplitAll<<<dim3(96, 96, 8), wb>>>(ws);

    ln_kernel<<<B_*T_*N_, 256>>>(cur_fea, n1w, n1b, x, xA);
    initmem_kernel<<<(B_*MEM_*C_/2 + 255)/256, 256>>>(x, memA, memAg);

    float* mcur = memA;
    float* mnxt = memB;

    for (int t = 1; t < T_; t++) {
        cudaEventRecord(eA, 0);
        cudaStreamWaitEvent(sS, eA, 0);

        // ---- stream S: m-chain (k first to release eK early) ----
        gemm64(memAg, wk, k_b, nullptr, K3, ROWS_, C_, C_, 32, sS);            // k -> K3
        cudaEventRecord(eK, sS);
        gemm64(memAg, wm1, m_b1, nullptr, hidMA, ROWS_, HID_, C_, 1|4, sS);    // fc1_m (600 blk)
        gemm64(hidMA, wm2, m_b2, memh, nullptr, ROWS_, C_, HID_, 2, sS);       // fc2_m

        // ---- legacy stream L: c-chain ----
        cudaMemsetAsync(ap, 0, B_*C_*sizeof(float), 0);
        ap_kernel<<<dim3((B_*C_ + 255)/256, 4), 256>>>(mcur, ap);
        apw2<<<dim3(HID_/128, B_), 128>>>(ap, c_w1, c_b1, bias2);
        const uint16_t* feaA = xA + (size_t)t * ROWS_ * 3 * C_;
        gemm64(feaA, wc1, bias2, nullptr, hidCA, ROWS_, HID_, C_, 1|4|8, 0);   // fc1_c (600 blk)
        gemm64(hidCA, wc2, c_b2, cg, cgA, ROWS_, C_, HID_, 2|4, 0);            // fc2_c
        cudaEventRecord(eCG, 0);
        cudaStreamWaitEvent(sS, eCG, 0);
        pack_cgT<<<dim3(3, 8, 64), wb, 0, sS>>>(cg, cgT3);                     // on S
        cudaEventRecord(eS2, sS);

        gemm64(cgA, wq, q_b, nullptr, Q3, ROWS_, C_, C_, 16, 0);               // q -> Q3
        cudaMemsetAsync(gate, 0, B_*H_*MEM_*sizeof(float), 0);
        cudaStreamWaitEvent(0, eK, 0);
        gemm_bat<<<dim3(2, 2, 64), 256, SMEM_BAT>>>(
            (const bf16*)Q3, (const bf16*)K3, oT3, gate, nullptr, 196, 196, 384, 0);
        cudaStreamWaitEvent(0, eS2, 0);
        gemm_bat<<<dim3(1, 2, 64), 256, SMEM_BAT>>>(
            (const bf16*)oT3, (const bf16*)cgT3, nullptr, nullptr, cA, 196, 96, 768, 1);

        gemm64(cA, wp1, p_b1, nullptr, hidCA, ROWS_, HID_, C_, 1|4, 0);        // fc1_p (600 blk)
        gemm64(hidCA, wp2, p_b2, c2, nullptr, ROWS_, C_, HID_, 2, 0);          // fc2_p

        float* dst = (t == T_ - 1) ? (float*)d_out : mnxt;
        final_kernel<<<B_*MEM_, 256>>>(c2, gate, memh, n2w, n2b, dst, memAg);

        float* tmp = mcur; mcur = mnxt; mnxt = tmp;
    }
}